// round 1
// baseline (speedup 1.0000x reference)
#include <cuda_runtime.h>
#include <math.h>

#define BATCH 128
#define H0 128
#define W0 128
#define C1 16
#define H1 64
#define C2 32
#define H2 32
#define NCODES 512
#define DIM 32

// Scratch (allocation-free rule: __device__ globals)
__device__ float g_h1[BATCH*C1*H1*H1];   // after conv1+pool+gelu  [B,16,64,64]
__device__ float g_h2[BATCH*C2*H2*H2];   // after conv2+pool       [B,32,32,32]
__device__ float g_g [BATCH*C1*H1*H1];   // after up+conv3+gelu    [B,16,64,64]
__device__ double g_loss;

__device__ __forceinline__ float gelu_exact(float v) {
    return 0.5f * v * (1.0f + erff(v * 0.70710678118654752440f));
}

// ---------------------------------------------------------------------------
// k1: conv1 (1->16, 3x3 SAME) + maxpool2 + gelu
// grid (8, B): tile = pooled 32 wide x 16 tall; block 256
// ---------------------------------------------------------------------------
__global__ __launch_bounds__(256) void k1(const float* __restrict__ x,
                                          const float* __restrict__ w1,
                                          const float* __restrict__ b1) {
    __shared__ float s_in[34*66];
    __shared__ float s_w[C1*9];
    __shared__ float s_b[C1];
    const int b = blockIdx.y;
    const int tile = blockIdx.x;
    const int px0 = (tile & 1) * 32;
    const int py0 = (tile >> 1) * 16;
    const int tid = threadIdx.x;
    if (tid < C1*9) s_w[tid] = w1[tid];
    if (tid < C1)   s_b[tid] = b1[tid];
    const float* xim = x + b * (H0*W0);
    for (int i = tid; i < 34*66; i += 256) {
        int r = i / 66, c = i - r*66;
        int gy = 2*py0 - 1 + r;
        int gx = 2*px0 - 1 + c;
        float v = 0.f;
        if ((unsigned)gy < (unsigned)H0 && (unsigned)gx < (unsigned)W0)
            v = xim[gy*W0 + gx];
        s_in[i] = v;
    }
    __syncthreads();
    #pragma unroll 1
    for (int p = tid; p < 32*16; p += 256) {
        int py = p >> 5, px = p & 31;
        float u[4][4];
        #pragma unroll
        for (int i = 0; i < 4; i++)
            #pragma unroll
            for (int j = 0; j < 4; j++)
                u[i][j] = s_in[(2*py+i)*66 + 2*px+j];
        int gy = py0 + py, gx = px0 + px;
        #pragma unroll
        for (int oc = 0; oc < C1; oc++) {
            float w00=s_w[oc*9+0],w01=s_w[oc*9+1],w02=s_w[oc*9+2];
            float w10=s_w[oc*9+3],w11=s_w[oc*9+4],w12=s_w[oc*9+5];
            float w20=s_w[oc*9+6],w21=s_w[oc*9+7],w22=s_w[oc*9+8];
            float m = -3.4e38f;
            #pragma unroll
            for (int dy = 0; dy < 2; dy++)
                #pragma unroll
                for (int dx = 0; dx < 2; dx++) {
                    float a = 0.f;
                    a = fmaf(w00, u[dy+0][dx+0], a);
                    a = fmaf(w01, u[dy+0][dx+1], a);
                    a = fmaf(w02, u[dy+0][dx+2], a);
                    a = fmaf(w10, u[dy+1][dx+0], a);
                    a = fmaf(w11, u[dy+1][dx+1], a);
                    a = fmaf(w12, u[dy+1][dx+2], a);
                    a = fmaf(w20, u[dy+2][dx+0], a);
                    a = fmaf(w21, u[dy+2][dx+1], a);
                    a = fmaf(w22, u[dy+2][dx+2], a);
                    m = fmaxf(m, a);
                }
            g_h1[((b*C1+oc)*H1 + gy)*H1 + gx] = gelu_exact(m + s_b[oc]);
        }
    }
}

// ---------------------------------------------------------------------------
// k2: conv2 (16->32, 3x3 SAME) + maxpool2
// grid (4, B): tile = pooled 32 wide x 8 tall; block 256 (1 pooled px/thread)
// dyn smem: in [16][18][66] + w2 [32*16*9] + b2[32]
// ---------------------------------------------------------------------------
#define K2_SMEM ((16*18*66 + 32*16*9 + 32)*4)
__global__ __launch_bounds__(256) void k2(const float* __restrict__ w2,
                                          const float* __restrict__ b2) {
    extern __shared__ float sm2[];
    float* s_in = sm2;
    float* s_w  = sm2 + 16*18*66;
    float* s_b  = s_w + 32*16*9;
    const int b = blockIdx.y;
    const int ry0 = blockIdx.x * 8;
    const int tid = threadIdx.x;
    for (int i = tid; i < 32*16*9; i += 256) s_w[i] = w2[i];
    if (tid < 32) s_b[tid] = b2[tid];
    for (int i = tid; i < 16*18*66; i += 256) {
        int ic = i / (18*66);
        int rem = i - ic*(18*66);
        int r = rem / 66, c = rem - r*66;
        int gy = 2*ry0 - 1 + r, gx = c - 1;
        float v = 0.f;
        if ((unsigned)gy < 64u && (unsigned)gx < 64u)
            v = g_h1[((b*16+ic)*64 + gy)*64 + gx];
        s_in[i] = v;
    }
    __syncthreads();
    const int py = tid >> 5, px = tid & 31;
    const int gy = ry0 + py, gx = px;
    #pragma unroll 1
    for (int ocg = 0; ocg < 4; ocg++) {
        float acc[8][4];
        #pragma unroll
        for (int o = 0; o < 8; o++)
            #pragma unroll
            for (int q = 0; q < 4; q++) acc[o][q] = 0.f;
        #pragma unroll 1
        for (int ic = 0; ic < 16; ic++) {
            const float* base = &s_in[(ic*18 + 2*py)*66 + 2*px];
            float u[4][4];
            #pragma unroll
            for (int i = 0; i < 4; i++)
                #pragma unroll
                for (int j = 0; j < 4; j++)
                    u[i][j] = base[i*66 + j];
            #pragma unroll
            for (int o = 0; o < 8; o++) {
                const float* w = &s_w[((ocg*8+o)*16 + ic)*9];
                float w00=w[0],w01=w[1],w02=w[2],w10=w[3],w11=w[4],w12=w[5],w20=w[6],w21=w[7],w22=w[8];
                #pragma unroll
                for (int dy = 0; dy < 2; dy++)
                    #pragma unroll
                    for (int dx = 0; dx < 2; dx++) {
                        float a = acc[o][dy*2+dx];
                        a = fmaf(w00, u[dy+0][dx+0], a);
                        a = fmaf(w01, u[dy+0][dx+1], a);
                        a = fmaf(w02, u[dy+0][dx+2], a);
                        a = fmaf(w10, u[dy+1][dx+0], a);
                        a = fmaf(w11, u[dy+1][dx+1], a);
                        a = fmaf(w12, u[dy+1][dx+2], a);
                        a = fmaf(w20, u[dy+2][dx+0], a);
                        a = fmaf(w21, u[dy+2][dx+1], a);
                        a = fmaf(w22, u[dy+2][dx+2], a);
                        acc[o][dy*2+dx] = a;
                    }
            }
        }
        #pragma unroll
        for (int o = 0; o < 8; o++) {
            int oc = ocg*8 + o;
            float m = fmaxf(fmaxf(acc[o][0], acc[o][1]), fmaxf(acc[o][2], acc[o][3])) + s_b[oc];
            g_h2[((b*32+oc)*32 + gy)*32 + gx] = m;
        }
    }
}

// ---------------------------------------------------------------------------
// k3: vector quantize. 2 pixels per thread; codebook in smem (float4 loads).
// grid 256 blocks x 256 threads; dyn smem: cb[512*32] + cn[512]
// ---------------------------------------------------------------------------
#define K3_SMEM ((NCODES*DIM + NCODES)*4)
__global__ __launch_bounds__(256) void k3(const float* __restrict__ codebook,
                                          float* __restrict__ out_idx) {
    extern __shared__ float sm3[];
    float* s_cb = sm3;
    float* s_cn = sm3 + NCODES*DIM;
    const int tid = threadIdx.x;
    for (int i = tid; i < NCODES*DIM; i += 256) s_cb[i] = codebook[i];
    __syncthreads();
    for (int k = tid; k < NCODES; k += 256) {
        float s = 0.f;
        #pragma unroll
        for (int d = 0; d < DIM; d++) s = fmaf(s_cb[k*DIM+d], s_cb[k*DIM+d], s);
        s_cn[k] = s;
    }
    __syncthreads();

    const int pid0 = blockIdx.x * 512 + tid;
    const int pid1 = pid0 + 256;
    float z0[DIM], z1[DIM];
    {
        int b0 = pid0 >> 10, n0 = pid0 & 1023;
        int b1_ = pid1 >> 10, n1 = pid1 & 1023;
        #pragma unroll
        for (int c = 0; c < DIM; c++) {
            z0[c] = g_h2[(b0*C2 + c)*1024 + n0];
            z1[c] = g_h2[(b1_*C2 + c)*1024 + n1];
        }
    }
    float zz0 = 0.f, zz1 = 0.f;
    #pragma unroll
    for (int c = 0; c < DIM; c++) { zz0 = fmaf(z0[c], z0[c], zz0); zz1 = fmaf(z1[c], z1[c], zz1); }

    float best0 = 3.4e38f, best1 = 3.4e38f;
    int i0 = 0, i1 = 0;
    const float4* cb4 = (const float4*)s_cb;
    #pragma unroll 1
    for (int k = 0; k < NCODES; k++) {
        float d0 = 0.f, d1 = 0.f;
        #pragma unroll
        for (int j = 0; j < 8; j++) {
            float4 cv = cb4[k*8 + j];
            d0 = fmaf(z0[4*j+0], cv.x, d0);
            d0 = fmaf(z0[4*j+1], cv.y, d0);
            d0 = fmaf(z0[4*j+2], cv.z, d0);
            d0 = fmaf(z0[4*j+3], cv.w, d0);
            d1 = fmaf(z1[4*j+0], cv.x, d1);
            d1 = fmaf(z1[4*j+1], cv.y, d1);
            d1 = fmaf(z1[4*j+2], cv.z, d1);
            d1 = fmaf(z1[4*j+3], cv.w, d1);
        }
        float e0 = fmaf(-2.f, d0, zz0) + s_cn[k];
        float e1 = fmaf(-2.f, d1, zz1) + s_cn[k];
        if (e0 < best0) { best0 = e0; i0 = k; }
        if (e1 < best1) { best1 = e1; i1 = k; }
    }
    out_idx[pid0] = (float)i0;
    out_idx[pid1] = (float)i1;

    float cl = 0.f;
    #pragma unroll
    for (int c = 0; c < DIM; c++) {
        float a = s_cb[i0*DIM + c] - z0[c];
        float bdf = s_cb[i1*DIM + c] - z1[c];
        cl = fmaf(a, a, cl);
        cl = fmaf(bdf, bdf, cl);
    }
    // block reduce -> one double atomic
    #pragma unroll
    for (int off = 16; off; off >>= 1) cl += __shfl_down_sync(0xffffffffu, cl, off);
    __shared__ float wsum[8];
    if ((tid & 31) == 0) wsum[tid >> 5] = cl;
    __syncthreads();
    if (tid == 0) {
        float s = 0.f;
        #pragma unroll
        for (int w = 0; w < 8; w++) s += wsum[w];
        atomicAdd(&g_loss, (double)s);
    }
}

// ---------------------------------------------------------------------------
// k4: nearest-upsample2(h2) + conv3 (32->16, 3x3 SAME) + gelu
// grid (4, B): output tile 32x32; block (16,16); thread = 2x2 micro-tile
// dyn smem: h tile [32][18][18] (zero-padded) + w3 [16*32*9] + b3[16]
// ---------------------------------------------------------------------------
#define K4_SMEM ((32*18*18 + 16*32*9 + 16)*4)
__global__ __launch_bounds__(256, 2) void k4(const float* __restrict__ w3,
                                             const float* __restrict__ b3) {
    extern __shared__ float sm4[];
    float* s_h = sm4;
    float* s_w = sm4 + 32*18*18;
    float* s_b = s_w + 16*32*9;
    const int b = blockIdx.y;
    const int tile = blockIdx.x;
    const int oy = (tile >> 1) * 32, ox = (tile & 1) * 32;
    const int hy0 = oy/2 - 1, hx0 = ox/2 - 1;
    const int tid = threadIdx.y*16 + threadIdx.x;
    for (int i = tid; i < 16*32*9; i += 256) s_w[i] = w3[i];
    if (tid < 16) s_b[tid] = b3[tid];
    for (int i = tid; i < 32*18*18; i += 256) {
        int ic = i / 324;
        int rem = i - ic*324;
        int r = rem / 18, c = rem - r*18;
        int hy = hy0 + r, hx = hx0 + c;
        float v = 0.f;
        if ((unsigned)hy < 32u && (unsigned)hx < 32u)
            v = g_h2[((b*32+ic)*32 + hy)*32 + hx];
        s_h[i] = v;
    }
    __syncthreads();
    const int ty = threadIdx.y, tx = threadIdx.x;
    const int y0 = oy + 2*ty, x0 = ox + 2*tx;
    float acc[16][4];
    #pragma unroll
    for (int o = 0; o < 16; o++)
        #pragma unroll
        for (int q = 0; q < 4; q++) acc[o][q] = 0.f;
    #pragma unroll 1
    for (int ic = 0; ic < 32; ic++) {
        float u[4][4];
        #pragma unroll
        for (int i = 0; i < 4; i++) {
            int rr = ((y0 - 1 + i) >> 1) - hy0;   // arithmetic shift handles p=-1
            #pragma unroll
            for (int j = 0; j < 4; j++) {
                int cc = ((x0 - 1 + j) >> 1) - hx0;
                u[i][j] = s_h[(ic*18 + rr)*18 + cc];
            }
        }
        #pragma unroll
        for (int o = 0; o < 16; o++) {
            const float* w = &s_w[(o*32 + ic)*9];
            float w00=w[0],w01=w[1],w02=w[2],w10=w[3],w11=w[4],w12=w[5],w20=w[6],w21=w[7],w22=w[8];
            #pragma unroll
            for (int dy = 0; dy < 2; dy++)
                #pragma unroll
                for (int dx = 0; dx < 2; dx++) {
                    float a = acc[o][dy*2+dx];
                    a = fmaf(w00, u[dy+0][dx+0], a);
                    a = fmaf(w01, u[dy+0][dx+1], a);
                    a = fmaf(w02, u[dy+0][dx+2], a);
                    a = fmaf(w10, u[dy+1][dx+0], a);
                    a = fmaf(w11, u[dy+1][dx+1], a);
                    a = fmaf(w12, u[dy+1][dx+2], a);
                    a = fmaf(w20, u[dy+2][dx+0], a);
                    a = fmaf(w21, u[dy+2][dx+1], a);
                    a = fmaf(w22, u[dy+2][dx+2], a);
                    acc[o][dy*2+dx] = a;
                }
        }
    }
    #pragma unroll
    for (int o = 0; o < 16; o++) {
        float bb = s_b[o];
        #pragma unroll
        for (int dy = 0; dy < 2; dy++)
            #pragma unroll
            for (int dx = 0; dx < 2; dx++)
                g_g[((b*16+o)*64 + (y0+dy))*64 + (x0+dx)] = gelu_exact(acc[o][dy*2+dx] + bb);
    }
}

// ---------------------------------------------------------------------------
// k5: nearest-upsample2(g) + conv4 (16->1, 3x3 SAME) + clip
// grid (16, B): output tile 32x32; block (16,16); thread = 2x2 micro-tile
// ---------------------------------------------------------------------------
__global__ __launch_bounds__(256) void k5(const float* __restrict__ w4,
                                          const float* __restrict__ b4,
                                          float* __restrict__ out) {
    __shared__ float s_g[16*18*18];
    __shared__ float s_w[144];
    __shared__ float s_bb[1];
    const int b = blockIdx.y;
    const int tile = blockIdx.x;
    const int oy = (tile >> 2) * 32, ox = (tile & 3) * 32;
    const int gy0 = oy/2 - 1, gx0 = ox/2 - 1;
    const int tid = threadIdx.y*16 + threadIdx.x;
    if (tid < 144) s_w[tid] = w4[tid];
    if (tid == 0) s_bb[0] = b4[0];
    for (int i = tid; i < 16*18*18; i += 256) {
        int ic = i / 324;
        int rem = i - ic*324;
        int r = rem / 18, c = rem - r*18;
        int gy = gy0 + r, gx = gx0 + c;
        float v = 0.f;
        if ((unsigned)gy < 64u && (unsigned)gx < 64u)
            v = g_g[((b*16+ic)*64 + gy)*64 + gx];
        s_g[i] = v;
    }
    __syncthreads();
    const int ty = threadIdx.y, tx = threadIdx.x;
    const int y0 = oy + 2*ty, x0 = ox + 2*tx;
    float acc[4] = {0.f, 0.f, 0.f, 0.f};
    #pragma unroll 1
    for (int ic = 0; ic < 16; ic++) {
        float u[4][4];
        #pragma unroll
        for (int i = 0; i < 4; i++) {
            int rr = ((y0 - 1 + i) >> 1) - gy0;
            #pragma unroll
            for (int j = 0; j < 4; j++) {
                int cc = ((x0 - 1 + j) >> 1) - gx0;
                u[i][j] = s_g[(ic*18 + rr)*18 + cc];
            }
        }
        const float* w = &s_w[ic*9];
        float w00=w[0],w01=w[1],w02=w[2],w10=w[3],w11=w[4],w12=w[5],w20=w[6],w21=w[7],w22=w[8];
        #pragma unroll
        for (int dy = 0; dy < 2; dy++)
            #pragma unroll
            for (int dx = 0; dx < 2; dx++) {
                float a = acc[dy*2+dx];
                a = fmaf(w00, u[dy+0][dx+0], a);
                a = fmaf(w01, u[dy+0][dx+1], a);
                a = fmaf(w02, u[dy+0][dx+2], a);
                a = fmaf(w10, u[dy+1][dx+0], a);
                a = fmaf(w11, u[dy+1][dx+1], a);
                a = fmaf(w12, u[dy+1][dx+2], a);
                a = fmaf(w20, u[dy+2][dx+0], a);
                a = fmaf(w21, u[dy+2][dx+1], a);
                a = fmaf(w22, u[dy+2][dx+2], a);
                acc[dy*2+dx] = a;
            }
    }
    float bb = s_bb[0];
    #pragma unroll
    for (int dy = 0; dy < 2; dy++)
        #pragma unroll
        for (int dx = 0; dx < 2; dx++) {
            float v = fminf(fmaxf(acc[dy*2+dx] + bb, -1.f), 1.f);
            out[(b*H0 + (y0+dy))*W0 + (x0+dx)] = v;
        }
}

// ---------------------------------------------------------------------------
__global__ void k_zero() { if (threadIdx.x == 0) g_loss = 0.0; }
__global__ void k_fin(float* __restrict__ out_loss) {
    if (threadIdx.x == 0)
        out_loss[0] = (float)(g_loss / (double)(BATCH * 1024 * DIM));
}

// ---------------------------------------------------------------------------
extern "C" void kernel_launch(void* const* d_in, const int* in_sizes, int n_in,
                              void* d_out, int out_size) {
    const float* x  = (const float*)d_in[0];
    const float* w1 = (const float*)d_in[1];
    const float* b1 = (const float*)d_in[2];
    const float* w2 = (const float*)d_in[3];
    const float* b2 = (const float*)d_in[4];
    const float* cb = (const float*)d_in[5];
    const float* w3 = (const float*)d_in[6];
    const float* b3 = (const float*)d_in[7];
    const float* w4 = (const float*)d_in[8];
    const float* b4 = (const float*)d_in[9];

    float* out      = (float*)d_out;
    float* out_idx  = out + BATCH*H0*W0;          // 2,097,152
    float* out_loss = out_idx + BATCH*H2*H2;      // +131,072

    cudaFuncSetAttribute(k2, cudaFuncAttributeMaxDynamicSharedMemorySize, K2_SMEM);
    cudaFuncSetAttribute(k3, cudaFuncAttributeMaxDynamicSharedMemorySize, K3_SMEM);
    cudaFuncSetAttribute(k4, cudaFuncAttributeMaxDynamicSharedMemorySize, K4_SMEM);

    k_zero<<<1, 32>>>();
    k1<<<dim3(8, BATCH), 256>>>(x, w1, b1);
    k2<<<dim3(4, BATCH), 256, K2_SMEM>>>(w2, b2);
    k3<<<256, 256, K3_SMEM>>>(cb, out_idx);
    k4<<<dim3(4, BATCH), dim3(16,16), K4_SMEM>>>(w3, b3);
    k5<<<dim3(16, BATCH), dim3(16,16)>>>(w4, b4, out);
    k_fin<<<1, 32>>>(out_loss);
}

// round 2
// speedup vs baseline: 1.1040x; 1.1040x over previous
#include <cuda_runtime.h>
#include <math.h>

#define BATCH 128
#define H0 128
#define W0 128
#define C1 16
#define H1 64
#define C2 32
#define H2 32
#define NCODES 512
#define DIM 32

typedef unsigned long long u64;

// Scratch (allocation-free rule: __device__ globals)
__device__ float g_h1[BATCH*C1*H1*H1];   // after conv1+pool+gelu  [B,16,64,64]
__device__ float g_h2[BATCH*C2*H2*H2];   // after conv2+pool       [B,32,32,32]
__device__ float g_g [BATCH*C1*H1*H1];   // after up+conv3+gelu    [B,16,64,64]
__device__ double g_loss;

__device__ __forceinline__ float gelu_exact(float v) {
    return 0.5f * v * (1.0f + erff(v * 0.70710678118654752440f));
}

// ---- packed fp32x2 helpers (Blackwell FFMA2 path) -------------------------
__device__ __forceinline__ u64 pk2(float lo, float hi) {
    u64 r; asm("mov.b64 %0, {%1,%2};" : "=l"(r) : "f"(lo), "f"(hi)); return r;
}
__device__ __forceinline__ void upk2(u64 v, float& lo, float& hi) {
    asm("mov.b64 {%0,%1}, %2;" : "=f"(lo), "=f"(hi) : "l"(v));
}
__device__ __forceinline__ u64 ffma2(u64 a, u64 b, u64 c) {
    u64 d; asm("fma.rn.f32x2 %0, %1, %2, %3;" : "=l"(d) : "l"(a), "l"(b), "l"(c)); return d;
}
__device__ __forceinline__ u64 fadd2(u64 a, u64 b) {
    u64 d; asm("add.rn.f32x2 %0, %1, %2;" : "=l"(d) : "l"(a), "l"(b)); return d;
}

// ---------------------------------------------------------------------------
// k1: conv1 (1->16, 3x3 SAME) + maxpool2 + gelu  (oc-paired f32x2)
// grid (8, B): tile = pooled 32 wide x 16 tall; block 256
// smem weights transposed [tap][oc] so oc-pairs are LDS.64
// ---------------------------------------------------------------------------
__global__ __launch_bounds__(256) void k1(const float* __restrict__ x,
                                          const float* __restrict__ w1,
                                          const float* __restrict__ b1) {
    __shared__ float s_in[34*66];
    __shared__ float s_w[9*C1];     // [t][oc]
    __shared__ float s_b[C1];
    const int b = blockIdx.y;
    const int tile = blockIdx.x;
    const int px0 = (tile & 1) * 32;
    const int py0 = (tile >> 1) * 16;
    const int tid = threadIdx.x;
    if (tid < C1*9) { int oc = tid / 9, t = tid - oc*9; s_w[t*C1 + oc] = w1[tid]; }
    if (tid < C1)   s_b[tid] = b1[tid];
    const float* xim = x + b * (H0*W0);
    for (int i = tid; i < 34*66; i += 256) {
        int r = i / 66, c = i - r*66;
        int gy = 2*py0 - 1 + r;
        int gx = 2*px0 - 1 + c;
        float v = 0.f;
        if ((unsigned)gy < (unsigned)H0 && (unsigned)gx < (unsigned)W0)
            v = xim[gy*W0 + gx];
        s_in[i] = v;
    }
    __syncthreads();
    #pragma unroll 1
    for (int p = tid; p < 32*16; p += 256) {
        int py = p >> 5, px = p & 31;
        u64 up[4][4];
        #pragma unroll
        for (int i = 0; i < 4; i++)
            #pragma unroll
            for (int j = 0; j < 4; j++) {
                float u = s_in[(2*py+i)*66 + 2*px+j];
                up[i][j] = pk2(u, u);
            }
        u64 acc[8][4];
        #pragma unroll
        for (int op = 0; op < 8; op++)
            #pragma unroll
            for (int q = 0; q < 4; q++) acc[op][q] = 0ull;
        #pragma unroll
        for (int t = 0; t < 9; t++) {
            int ky = t / 3, kx = t - ky*3;
            #pragma unroll
            for (int op = 0; op < 8; op++) {
                u64 w = *(const u64*)&s_w[t*C1 + op*2];
                #pragma unroll
                for (int dy = 0; dy < 2; dy++)
                    #pragma unroll
                    for (int dx = 0; dx < 2; dx++)
                        acc[op][dy*2+dx] = ffma2(up[dy+ky][dx+kx], w, acc[op][dy*2+dx]);
            }
        }
        int gy = py0 + py, gx = px0 + px;
        #pragma unroll
        for (int op = 0; op < 8; op++) {
            float l0,h0,l1,h1,l2,h2,l3,h3;
            upk2(acc[op][0], l0, h0); upk2(acc[op][1], l1, h1);
            upk2(acc[op][2], l2, h2); upk2(acc[op][3], l3, h3);
            float mlo = fmaxf(fmaxf(l0,l1), fmaxf(l2,l3)) + s_b[op*2+0];
            float mhi = fmaxf(fmaxf(h0,h1), fmaxf(h2,h3)) + s_b[op*2+1];
            g_h1[((b*C1+op*2+0)*H1 + gy)*H1 + gx] = gelu_exact(mlo);
            g_h1[((b*C1+op*2+1)*H1 + gy)*H1 + gx] = gelu_exact(mhi);
        }
    }
}

// ---------------------------------------------------------------------------
// k2: conv2 (16->32, 3x3 SAME) + maxpool2  (oc-paired f32x2)
// grid (4, B): tile = pooled 32 wide x 8 tall; block 256 (1 pooled px/thread)
// smem: in [16][18][66] + w2 transposed [ic][t][oc=32] + b2[32]
// ---------------------------------------------------------------------------
#define K2_SMEM ((16*18*66 + 16*9*32 + 32)*4)
__global__ __launch_bounds__(256) void k2(const float* __restrict__ w2,
                                          const float* __restrict__ b2) {
    extern __shared__ float sm2[];
    float* s_in = sm2;
    float* s_w  = sm2 + 16*18*66;      // [ic][t][oc]
    float* s_b  = s_w + 16*9*32;
    const int b = blockIdx.y;
    const int ry0 = blockIdx.x * 8;
    const int tid = threadIdx.x;
    for (int i = tid; i < 32*16*9; i += 256) {
        int o = i / 144; int rem = i - o*144; int ic = rem / 9; int t = rem - ic*9;
        s_w[(ic*9 + t)*32 + o] = w2[i];
    }
    if (tid < 32) s_b[tid] = b2[tid];
    for (int i = tid; i < 16*18*66; i += 256) {
        int ic = i / (18*66);
        int rem = i - ic*(18*66);
        int r = rem / 66, c = rem - r*66;
        int gy = 2*ry0 - 1 + r, gx = c - 1;
        float v = 0.f;
        if ((unsigned)gy < 64u && (unsigned)gx < 64u)
            v = g_h1[((b*16+ic)*64 + gy)*64 + gx];
        s_in[i] = v;
    }
    __syncthreads();
    const int py = tid >> 5, px = tid & 31;
    const int gy = ry0 + py, gx = px;
    #pragma unroll 1
    for (int ocg = 0; ocg < 4; ocg++) {
        u64 acc[4][4];
        #pragma unroll
        for (int op = 0; op < 4; op++)
            #pragma unroll
            for (int q = 0; q < 4; q++) acc[op][q] = 0ull;
        #pragma unroll 1
        for (int ic = 0; ic < 16; ic++) {
            const float* base = &s_in[(ic*18 + 2*py)*66 + 2*px];
            u64 up[4][4];
            #pragma unroll
            for (int i = 0; i < 4; i++)
                #pragma unroll
                for (int j = 0; j < 4; j++) {
                    float u = base[i*66 + j];
                    up[i][j] = pk2(u, u);
                }
            #pragma unroll
            for (int t = 0; t < 9; t++) {
                int ky = t / 3, kx = t - ky*3;
                #pragma unroll
                for (int op = 0; op < 4; op++) {
                    u64 w = *(const u64*)&s_w[(ic*9 + t)*32 + ocg*8 + op*2];
                    #pragma unroll
                    for (int dy = 0; dy < 2; dy++)
                        #pragma unroll
                        for (int dx = 0; dx < 2; dx++)
                            acc[op][dy*2+dx] = ffma2(up[dy+ky][dx+kx], w, acc[op][dy*2+dx]);
                }
            }
        }
        #pragma unroll
        for (int op = 0; op < 4; op++) {
            float l0,h0,l1,h1,l2,h2,l3,h3;
            upk2(acc[op][0], l0, h0); upk2(acc[op][1], l1, h1);
            upk2(acc[op][2], l2, h2); upk2(acc[op][3], l3, h3);
            int oc = ocg*8 + op*2;
            float mlo = fmaxf(fmaxf(l0,l1), fmaxf(l2,l3)) + s_b[oc+0];
            float mhi = fmaxf(fmaxf(h0,h1), fmaxf(h2,h3)) + s_b[oc+1];
            g_h2[((b*32+oc+0)*32 + gy)*32 + gx] = mlo;
            g_h2[((b*32+oc+1)*32 + gy)*32 + gx] = mhi;
        }
    }
}

// ---------------------------------------------------------------------------
// k3: vector quantize. 2 pixels per thread; codebook in smem.
// f32x2: z packed as (z[2j],z[2j+1]); codebook rows are natural f32x2 pairs.
// grid 256 blocks x 256 threads; dyn smem: cb[512*32] + cn[512]
// ---------------------------------------------------------------------------
#define K3_SMEM ((NCODES*DIM + NCODES)*4)
__global__ __launch_bounds__(256) void k3(const float* __restrict__ codebook,
                                          float* __restrict__ out_idx) {
    extern __shared__ float sm3[];
    float* s_cb = sm3;
    float* s_cn = sm3 + NCODES*DIM;
    const int tid = threadIdx.x;
    for (int i = tid; i < NCODES*DIM; i += 256) s_cb[i] = codebook[i];
    __syncthreads();
    for (int k = tid; k < NCODES; k += 256) {
        float s = 0.f;
        #pragma unroll
        for (int d = 0; d < DIM; d++) s = fmaf(s_cb[k*DIM+d], s_cb[k*DIM+d], s);
        s_cn[k] = s;
    }
    __syncthreads();

    const int pid0 = blockIdx.x * 512 + tid;
    const int pid1 = pid0 + 256;
    float z0[DIM], z1[DIM];
    {
        int b0 = pid0 >> 10, n0 = pid0 & 1023;
        int b1_ = pid1 >> 10, n1 = pid1 & 1023;
        #pragma unroll
        for (int c = 0; c < DIM; c++) {
            z0[c] = g_h2[(b0*C2 + c)*1024 + n0];
            z1[c] = g_h2[(b1_*C2 + c)*1024 + n1];
        }
    }
    float zz0 = 0.f, zz1 = 0.f;
    #pragma unroll
    for (int c = 0; c < DIM; c++) { zz0 = fmaf(z0[c], z0[c], zz0); zz1 = fmaf(z1[c], z1[c], zz1); }

    u64 zp0[16], zp1[16];
    #pragma unroll
    for (int j = 0; j < 16; j++) {
        zp0[j] = pk2(z0[2*j], z0[2*j+1]);
        zp1[j] = pk2(z1[2*j], z1[2*j+1]);
    }

    float best0 = 3.4e38f, best1 = 3.4e38f;
    int i0 = 0, i1 = 0;
    const ulonglong2* cb2 = (const ulonglong2*)s_cb;
    #pragma unroll 2
    for (int k = 0; k < NCODES; k++) {
        u64 a0 = 0ull, b0 = 0ull, a1 = 0ull, b1 = 0ull;   // 4 chains
        #pragma unroll
        for (int j = 0; j < 4; j++) {
            ulonglong2 c0 = cb2[k*8 + 2*j];
            ulonglong2 c1 = cb2[k*8 + 2*j + 1];
            a0 = ffma2(zp0[4*j+0], c0.x, a0);
            b0 = ffma2(zp0[4*j+1], c0.y, b0);
            a0 = ffma2(zp0[4*j+2], c1.x, a0);
            b0 = ffma2(zp0[4*j+3], c1.y, b0);
            a1 = ffma2(zp1[4*j+0], c0.x, a1);
            b1 = ffma2(zp1[4*j+1], c0.y, b1);
            a1 = ffma2(zp1[4*j+2], c1.x, a1);
            b1 = ffma2(zp1[4*j+3], c1.y, b1);
        }
        float lo, hi;
        float cn = s_cn[k];
        upk2(fadd2(a0, b0), lo, hi);
        float e0 = fmaf(-2.f, lo + hi, zz0) + cn;
        upk2(fadd2(a1, b1), lo, hi);
        float e1 = fmaf(-2.f, lo + hi, zz1) + cn;
        if (e0 < best0) { best0 = e0; i0 = k; }
        if (e1 < best1) { best1 = e1; i1 = k; }
    }
    out_idx[pid0] = (float)i0;
    out_idx[pid1] = (float)i1;

    float cl = 0.f;
    #pragma unroll
    for (int c = 0; c < DIM; c++) {
        float a = s_cb[i0*DIM + c] - z0[c];
        float bdf = s_cb[i1*DIM + c] - z1[c];
        cl = fmaf(a, a, cl);
        cl = fmaf(bdf, bdf, cl);
    }
    #pragma unroll
    for (int off = 16; off; off >>= 1) cl += __shfl_down_sync(0xffffffffu, cl, off);
    __shared__ float wsum[8];
    if ((tid & 31) == 0) wsum[tid >> 5] = cl;
    __syncthreads();
    if (tid == 0) {
        float s = 0.f;
        #pragma unroll
        for (int w = 0; w < 8; w++) s += wsum[w];
        atomicAdd(&g_loss, (double)s);
    }
}

// ---------------------------------------------------------------------------
// k4: nearest-upsample2(h2) + conv3 (32->16, 3x3 SAME) + gelu (oc-paired f32x2)
// grid (4, B): output tile 32x32; block (16,16); thread = 2x2 micro-tile
// dyn smem: h tile [32][18][18] + w3 transposed [ic][t][oc=16] + b3[16]
// ---------------------------------------------------------------------------
#define K4_SMEM ((32*18*18 + 32*9*16 + 16)*4)
__global__ __launch_bounds__(256, 2) void k4(const float* __restrict__ w3,
                                             const float* __restrict__ b3) {
    extern __shared__ float sm4[];
    float* s_h = sm4;
    float* s_w = sm4 + 32*18*18;     // [ic][t][oc]
    float* s_b = s_w + 32*9*16;
    const int b = blockIdx.y;
    const int tile = blockIdx.x;
    const int oy = (tile >> 1) * 32, ox = (tile & 1) * 32;
    const int hy0 = oy/2 - 1, hx0 = ox/2 - 1;
    const int tid = threadIdx.y*16 + threadIdx.x;
    for (int i = tid; i < 16*32*9; i += 256) {
        int o = i / 288; int rem = i - o*288; int ic = rem / 9; int t = rem - ic*9;
        s_w[(ic*9 + t)*16 + o] = w3[i];
    }
    if (tid < 16) s_b[tid] = b3[tid];
    for (int i = tid; i < 32*18*18; i += 256) {
        int ic = i / 324;
        int rem = i - ic*324;
        int r = rem / 18, c = rem - r*18;
        int hy = hy0 + r, hx = hx0 + c;
        float v = 0.f;
        if ((unsigned)hy < 32u && (unsigned)hx < 32u)
            v = g_h2[((b*32+ic)*32 + hy)*32 + hx];
        s_h[i] = v;
    }
    __syncthreads();
    const int ty = threadIdx.y, tx = threadIdx.x;
    const int y0 = oy + 2*ty, x0 = ox + 2*tx;
    int rr[4], cc[4];
    #pragma unroll
    for (int i = 0; i < 4; i++) {
        rr[i] = ((y0 - 1 + i) >> 1) - hy0;   // arithmetic shift handles -1
        cc[i] = ((x0 - 1 + i) >> 1) - hx0;
    }
    #pragma unroll 1
    for (int ocg = 0; ocg < 2; ocg++) {
        u64 acc[4][4];
        #pragma unroll
        for (int op = 0; op < 4; op++)
            #pragma unroll
            for (int q = 0; q < 4; q++) acc[op][q] = 0ull;
        #pragma unroll 1
        for (int ic = 0; ic < 32; ic++) {
            u64 up[4][4];
            #pragma unroll
            for (int i = 0; i < 4; i++)
                #pragma unroll
                for (int j = 0; j < 4; j++) {
                    float u = s_h[(ic*18 + rr[i])*18 + cc[j]];
                    up[i][j] = pk2(u, u);
                }
            #pragma unroll
            for (int t = 0; t < 9; t++) {
                int ky = t / 3, kx = t - ky*3;
                #pragma unroll
                for (int op = 0; op < 4; op++) {
                    u64 w = *(const u64*)&s_w[(ic*9 + t)*16 + ocg*8 + op*2];
                    #pragma unroll
                    for (int dy = 0; dy < 2; dy++)
                        #pragma unroll
                        for (int dx = 0; dx < 2; dx++)
                            acc[op][dy*2+dx] = ffma2(up[dy+ky][dx+kx], w, acc[op][dy*2+dx]);
                }
            }
        }
        #pragma unroll
        for (int op = 0; op < 4; op++) {
            int oc = ocg*8 + op*2;
            float blo = s_b[oc], bhi = s_b[oc+1];
            #pragma unroll
            for (int dy = 0; dy < 2; dy++)
                #pragma unroll
                for (int dx = 0; dx < 2; dx++) {
                    float lo, hi;
                    upk2(acc[op][dy*2+dx], lo, hi);
                    g_g[((b*16+oc+0)*64 + (y0+dy))*64 + (x0+dx)] = gelu_exact(lo + blo);
                    g_g[((b*16+oc+1)*64 + (y0+dy))*64 + (x0+dx)] = gelu_exact(hi + bhi);
                }
        }
    }
}

// ---------------------------------------------------------------------------
// k5: nearest-upsample2(g) + conv4 (16->1, 3x3 SAME) + clip
// grid (16, B): output tile 32x32; block (16,16); thread = 2x2 micro-tile
// ---------------------------------------------------------------------------
__global__ __launch_bounds__(256) void k5(const float* __restrict__ w4,
                                          const float* __restrict__ b4,
                                          float* __restrict__ out) {
    __shared__ float s_g[16*18*18];
    __shared__ float s_w[144];
    __shared__ float s_bb[1];
    const int b = blockIdx.y;
    const int tile = blockIdx.x;
    const int oy = (tile >> 2) * 32, ox = (tile & 3) * 32;
    const int gy0 = oy/2 - 1, gx0 = ox/2 - 1;
    const int tid = threadIdx.y*16 + threadIdx.x;
    if (tid < 144) s_w[tid] = w4[tid];
    if (tid == 0) s_bb[0] = b4[0];
    for (int i = tid; i < 16*18*18; i += 256) {
        int ic = i / 324;
        int rem = i - ic*324;
        int r = rem / 18, c = rem - r*18;
        int gy = gy0 + r, gx = gx0 + c;
        float v = 0.f;
        if ((unsigned)gy < 64u && (unsigned)gx < 64u)
            v = g_g[((b*16+ic)*64 + gy)*64 + gx];
        s_g[i] = v;
    }
    __syncthreads();
    const int ty = threadIdx.y, tx = threadIdx.x;
    const int y0 = oy + 2*ty, x0 = ox + 2*tx;
    float acc[4] = {0.f, 0.f, 0.f, 0.f};
    #pragma unroll 1
    for (int ic = 0; ic < 16; ic++) {
        float u[4][4];
        #pragma unroll
        for (int i = 0; i < 4; i++) {
            int rr = ((y0 - 1 + i) >> 1) - gy0;
            #pragma unroll
            for (int j = 0; j < 4; j++) {
                int cc = ((x0 - 1 + j) >> 1) - gx0;
                u[i][j] = s_g[(ic*18 + rr)*18 + cc];
            }
        }
        const float* w = &s_w[ic*9];
        float w00=w[0],w01=w[1],w02=w[2],w10=w[3],w11=w[4],w12=w[5],w20=w[6],w21=w[7],w22=w[8];
        #pragma unroll
        for (int dy = 0; dy < 2; dy++)
            #pragma unroll
            for (int dx = 0; dx < 2; dx++) {
                float a = acc[dy*2+dx];
                a = fmaf(w00, u[dy+0][dx+0], a);
                a = fmaf(w01, u[dy+0][dx+1], a);
                a = fmaf(w02, u[dy+0][dx+2], a);
                a = fmaf(w10, u[dy+1][dx+0], a);
                a = fmaf(w11, u[dy+1][dx+1], a);
                a = fmaf(w12, u[dy+1][dx+2], a);
                a = fmaf(w20, u[dy+2][dx+0], a);
                a = fmaf(w21, u[dy+2][dx+1], a);
                a = fmaf(w22, u[dy+2][dx+2], a);
                acc[dy*2+dx] = a;
            }
    }
    float bb = s_bb[0];
    #pragma unroll
    for (int dy = 0; dy < 2; dy++)
        #pragma unroll
        for (int dx = 0; dx < 2; dx++) {
            float v = fminf(fmaxf(acc[dy*2+dx] + bb, -1.f), 1.f);
            out[(b*H0 + (y0+dy))*W0 + (x0+dx)] = v;
        }
}

// ---------------------------------------------------------------------------
__global__ void k_zero() { if (threadIdx.x == 0) g_loss = 0.0; }
__global__ void k_fin(float* __restrict__ out_loss) {
    if (threadIdx.x == 0)
        out_loss[0] = (float)(g_loss / (double)(BATCH * 1024 * DIM));
}

// ---------------------------------------------------------------------------
extern "C" void kernel_launch(void* const* d_in, const int* in_sizes, int n_in,
                              void* d_out, int out_size) {
    const float* x  = (const float*)d_in[0];
    const float* w1 = (const float*)d_in[1];
    const float* b1 = (const float*)d_in[2];
    const float* w2 = (const float*)d_in[3];
    const float* b2 = (const float*)d_in[4];
    const float* cb = (const float*)d_in[5];
    const float* w3 = (const float*)d_in[6];
    const float* b3 = (const float*)d_in[7];
    const float* w4 = (const float*)d_in[8];
    const float* b4 = (const float*)d_in[9];

    float* out      = (float*)d_out;
    float* out_idx  = out + BATCH*H0*W0;          // 2,097,152
    float* out_loss = out_idx + BATCH*H2*H2;      // +131,072

    cudaFuncSetAttribute(k2, cudaFuncAttributeMaxDynamicSharedMemorySize, K2_SMEM);
    cudaFuncSetAttribute(k3, cudaFuncAttributeMaxDynamicSharedMemorySize, K3_SMEM);
    cudaFuncSetAttribute(k4, cudaFuncAttributeMaxDynamicSharedMemorySize, K4_SMEM);

    k_zero<<<1, 32>>>();
    k1<<<dim3(8, BATCH), 256>>>(x, w1, b1);
    k2<<<dim3(4, BATCH), 256, K2_SMEM>>>(w2, b2);
    k3<<<256, 256, K3_SMEM>>>(cb, out_idx);
    k4<<<dim3(4, BATCH), dim3(16,16), K4_SMEM>>>(w3, b3);
    k5<<<dim3(16, BATCH), dim3(16,16)>>>(w4, b4, out);
    k_fin<<<1, 32>>>(out_loss);
}

// round 3
// speedup vs baseline: 1.2039x; 1.0904x over previous
#include <cuda_runtime.h>
#include <math.h>

#define BATCH 128
#define H0 128
#define W0 128
#define C1 16
#define H1 64
#define C2 32
#define H2 32
#define NCODES 512
#define DIM 32

typedef unsigned long long u64;

// Scratch (allocation-free rule: __device__ globals)
__device__ float g_h1[BATCH*C1*H1*H1];   // after conv1+pool+gelu  [B,16,64,64]
__device__ float g_h2[BATCH*C2*H2*H2];   // after conv2+pool       [B,32,32,32]
__device__ float g_g [BATCH*C1*H1*H1];   // after up+conv3+gelu    [B,16,64,64]
__device__ double g_loss;

__device__ __forceinline__ float gelu_exact(float v) {
    return 0.5f * v * (1.0f + erff(v * 0.70710678118654752440f));
}

// ---- packed fp32x2 helpers (Blackwell FFMA2 path) -------------------------
__device__ __forceinline__ u64 pk2(float lo, float hi) {
    u64 r; asm("mov.b64 %0, {%1,%2};" : "=l"(r) : "f"(lo), "f"(hi)); return r;
}
__device__ __forceinline__ void upk2(u64 v, float& lo, float& hi) {
    asm("mov.b64 {%0,%1}, %2;" : "=f"(lo), "=f"(hi) : "l"(v));
}
__device__ __forceinline__ u64 ffma2(u64 a, u64 b, u64 c) {
    u64 d; asm("fma.rn.f32x2 %0, %1, %2, %3;" : "=l"(d) : "l"(a), "l"(b), "l"(c)); return d;
}

// ---------------------------------------------------------------------------
// k1: conv1 (1->16, 3x3 SAME) + maxpool2 + gelu  (oc-paired f32x2)
// grid (8, B): tile = pooled 32 wide x 16 tall; block 256
// ---------------------------------------------------------------------------
__global__ __launch_bounds__(256) void k1(const float* __restrict__ x,
                                          const float* __restrict__ w1,
                                          const float* __restrict__ b1) {
    __shared__ __align__(16) float s_in[34*66];
    __shared__ __align__(16) float s_w[9*C1];     // [t][oc]
    __shared__ float s_b[C1];
    const int b = blockIdx.y;
    const int tile = blockIdx.x;
    const int px0 = (tile & 1) * 32;
    const int py0 = (tile >> 1) * 16;
    const int tid = threadIdx.x;
    if (tid < C1*9) { int oc = tid / 9, t = tid - oc*9; s_w[t*C1 + oc] = w1[tid]; }
    if (tid < C1)   s_b[tid] = b1[tid];
    const float* xim = x + b * (H0*W0);
    for (int i = tid; i < 34*66; i += 256) {
        int r = i / 66, c = i - r*66;
        int gy = 2*py0 - 1 + r;
        int gx = 2*px0 - 1 + c;
        float v = 0.f;
        if ((unsigned)gy < (unsigned)H0 && (unsigned)gx < (unsigned)W0)
            v = xim[gy*W0 + gx];
        s_in[i] = v;
    }
    __syncthreads();
    #pragma unroll 1
    for (int p = tid; p < 32*16; p += 256) {
        int py = p >> 5, px = p & 31;
        u64 up[4][4];
        #pragma unroll
        for (int i = 0; i < 4; i++) {
            float2 a = *(const float2*)&s_in[(2*py+i)*66 + 2*px];
            float2 c = *(const float2*)&s_in[(2*py+i)*66 + 2*px + 2];
            up[i][0] = pk2(a.x, a.x); up[i][1] = pk2(a.y, a.y);
            up[i][2] = pk2(c.x, c.x); up[i][3] = pk2(c.y, c.y);
        }
        u64 acc[8][4];
        #pragma unroll
        for (int op = 0; op < 8; op++)
            #pragma unroll
            for (int q = 0; q < 4; q++) acc[op][q] = 0ull;
        #pragma unroll
        for (int t = 0; t < 9; t++) {
            int ky = t / 3, kx = t - ky*3;
            ulonglong2 wA = *(const ulonglong2*)&s_w[t*C1 + 0];
            ulonglong2 wB = *(const ulonglong2*)&s_w[t*C1 + 4];
            ulonglong2 wC = *(const ulonglong2*)&s_w[t*C1 + 8];
            ulonglong2 wD = *(const ulonglong2*)&s_w[t*C1 + 12];
            u64 wv[8] = {wA.x, wA.y, wB.x, wB.y, wC.x, wC.y, wD.x, wD.y};
            #pragma unroll
            for (int op = 0; op < 8; op++)
                #pragma unroll
                for (int dy = 0; dy < 2; dy++)
                    #pragma unroll
                    for (int dx = 0; dx < 2; dx++)
                        acc[op][dy*2+dx] = ffma2(up[dy+ky][dx+kx], wv[op], acc[op][dy*2+dx]);
        }
        int gy = py0 + py, gx = px0 + px;
        #pragma unroll
        for (int op = 0; op < 8; op++) {
            float l0,h0,l1,h1,l2,h2,l3,h3;
            upk2(acc[op][0], l0, h0); upk2(acc[op][1], l1, h1);
            upk2(acc[op][2], l2, h2); upk2(acc[op][3], l3, h3);
            float mlo = fmaxf(fmaxf(l0,l1), fmaxf(l2,l3)) + s_b[op*2+0];
            float mhi = fmaxf(fmaxf(h0,h1), fmaxf(h2,h3)) + s_b[op*2+1];
            g_h1[((b*C1+op*2+0)*H1 + gy)*H1 + gx] = gelu_exact(mlo);
            g_h1[((b*C1+op*2+1)*H1 + gy)*H1 + gx] = gelu_exact(mhi);
        }
    }
}

// ---------------------------------------------------------------------------
// k2: conv2 (16->32, 3x3 SAME) + maxpool2  (oc-paired f32x2, 2 passes of 16 oc)
// grid (4, B): tile = pooled 32 wide x 8 tall; block 256 (1 pooled px/thread)
// smem: in [16][18][66] + w2 transposed [ic][t][oc=32] + b2[32]
// ---------------------------------------------------------------------------
#define K2_SMEM ((16*18*66 + 16*9*32 + 32)*4)
__global__ __launch_bounds__(256) void k2(const float* __restrict__ w2,
                                          const float* __restrict__ b2) {
    extern __shared__ __align__(16) float sm2[];
    float* s_in = sm2;
    float* s_w  = sm2 + 16*18*66;      // [ic][t][oc]
    float* s_b  = s_w + 16*9*32;
    const int b = blockIdx.y;
    const int ry0 = blockIdx.x * 8;
    const int tid = threadIdx.x;
    for (int i = tid; i < 32*16*9; i += 256) {
        int o = i / 144; int rem = i - o*144; int ic = rem / 9; int t = rem - ic*9;
        s_w[(ic*9 + t)*32 + o] = w2[i];
    }
    if (tid < 32) s_b[tid] = b2[tid];
    for (int i = tid; i < 16*18*66; i += 256) {
        int ic = i / (18*66);
        int rem = i - ic*(18*66);
        int r = rem / 66, c = rem - r*66;
        int gy = 2*ry0 - 1 + r, gx = c - 1;
        float v = 0.f;
        if ((unsigned)gy < 64u && (unsigned)gx < 64u)
            v = g_h1[((b*16+ic)*64 + gy)*64 + gx];
        s_in[i] = v;
    }
    __syncthreads();
    const int py = tid >> 5, px = tid & 31;
    const int gy = ry0 + py, gx = px;
    #pragma unroll 1
    for (int pass = 0; pass < 2; pass++) {
        u64 acc[8][4];
        #pragma unroll
        for (int op = 0; op < 8; op++)
            #pragma unroll
            for (int q = 0; q < 4; q++) acc[op][q] = 0ull;
        #pragma unroll 1
        for (int ic = 0; ic < 16; ic++) {
            const float* base = &s_in[(ic*18 + 2*py)*66 + 2*px];
            u64 up[4][4];
            #pragma unroll
            for (int i = 0; i < 4; i++) {
                float2 a = *(const float2*)&base[i*66];
                float2 c = *(const float2*)&base[i*66 + 2];
                up[i][0] = pk2(a.x, a.x); up[i][1] = pk2(a.y, a.y);
                up[i][2] = pk2(c.x, c.x); up[i][3] = pk2(c.y, c.y);
            }
            #pragma unroll
            for (int t = 0; t < 9; t++) {
                int ky = t / 3, kx = t - ky*3;
                const float* wp = &s_w[(ic*9 + t)*32 + pass*16];
                ulonglong2 wA = *(const ulonglong2*)&wp[0];
                ulonglong2 wB = *(const ulonglong2*)&wp[4];
                ulonglong2 wC = *(const ulonglong2*)&wp[8];
                ulonglong2 wD = *(const ulonglong2*)&wp[12];
                u64 wv[8] = {wA.x, wA.y, wB.x, wB.y, wC.x, wC.y, wD.x, wD.y};
                #pragma unroll
                for (int op = 0; op < 8; op++)
                    #pragma unroll
                    for (int dy = 0; dy < 2; dy++)
                        #pragma unroll
                        for (int dx = 0; dx < 2; dx++)
                            acc[op][dy*2+dx] = ffma2(up[dy+ky][dx+kx], wv[op], acc[op][dy*2+dx]);
            }
        }
        #pragma unroll
        for (int op = 0; op < 8; op++) {
            float l0,h0,l1,h1,l2,h2,l3,h3;
            upk2(acc[op][0], l0, h0); upk2(acc[op][1], l1, h1);
            upk2(acc[op][2], l2, h2); upk2(acc[op][3], l3, h3);
            int oc = pass*16 + op*2;
            float mlo = fmaxf(fmaxf(l0,l1), fmaxf(l2,l3)) + s_b[oc+0];
            float mhi = fmaxf(fmaxf(h0,h1), fmaxf(h2,h3)) + s_b[oc+1];
            g_h2[((b*32+oc+0)*32 + gy)*32 + gx] = mlo;
            g_h2[((b*32+oc+1)*32 + gy)*32 + gx] = mhi;
        }
    }
}

// ---------------------------------------------------------------------------
// k3: vector quantize as a smem GEMM.
// block = 128 pixels x 512 codes; 256 threads; thread = 8px x 8codes microtile
// comparator e' = cn/2 - dot  (zz constant per pixel -> same argmin order)
// smem: cbT [32][516] + zT [32][128] + cn2[512] + reduce buffers
// ---------------------------------------------------------------------------
#define CBT_STRIDE 516
#define K3_SMEM ((32*CBT_STRIDE + 32*128 + 512 + 16*128*2)*4)
__global__ __launch_bounds__(256, 2) void k3(const float* __restrict__ codebook,
                                             float* __restrict__ out_idx) {
    extern __shared__ __align__(16) float sm3[];
    float* s_cbT = sm3;                         // [32][516]
    float* s_zT  = s_cbT + 32*CBT_STRIDE;       // [32][128]
    float* s_cn2 = s_zT + 32*128;               // [512]
    float* s_re  = s_cn2 + 512;                 // [16][128]
    int*   s_ri  = (int*)(s_re + 16*128);       // [16][128]
    const int tid = threadIdx.x;
    const int P0 = blockIdx.x * 128;            // 128 pixels, same image (1024 % 128 == 0)
    const int b  = P0 >> 10;
    const int n0 = P0 & 1023;

    // stage codebook transposed + z transposed
    for (int i = tid; i < NCODES*DIM; i += 256) {
        int k = i >> 5, d = i & 31;
        s_cbT[d*CBT_STRIDE + k] = codebook[i];
    }
    for (int i = tid; i < 32*128; i += 256) {
        int d = i >> 7, px = i & 127;
        s_zT[d*128 + px] = g_h2[(b*C2 + d)*1024 + n0 + px];
    }
    __syncthreads();
    for (int k = tid; k < NCODES; k += 256) {
        float s = 0.f;
        #pragma unroll
        for (int d = 0; d < DIM; d++) {
            float c = s_cbT[d*CBT_STRIDE + k];
            s = fmaf(c, c, s);
        }
        s_cn2[k] = 0.5f * s;
    }
    __syncthreads();

    const int tx = tid & 15, ty = tid >> 4;
    const int px0 = tx * 8;
    float best[8]; int bidx[8];
    #pragma unroll
    for (int i = 0; i < 8; i++) { best[i] = 3.4e38f; bidx[i] = 0; }

    #pragma unroll 1
    for (int tile = 0; tile < 4; tile++) {
        const int c0 = ty*32 + tile*8;
        u64 acc[8][4];
        #pragma unroll
        for (int j = 0; j < 8; j++)
            #pragma unroll
            for (int pp = 0; pp < 4; pp++) acc[j][pp] = 0ull;
        #pragma unroll 4
        for (int d = 0; d < 32; d++) {
            const float* zr = &s_zT[d*128 + px0];
            ulonglong2 za = *(const ulonglong2*)zr;          // px 0-3 packed
            ulonglong2 zb = *(const ulonglong2*)(zr + 4);    // px 4-7 packed
            u64 zp[4] = {za.x, za.y, zb.x, zb.y};
            const float* cr = &s_cbT[d*CBT_STRIDE + c0];
            float4 cA = *(const float4*)cr;
            float4 cB = *(const float4*)(cr + 4);
            u64 wv[8];
            wv[0] = pk2(cA.x, cA.x); wv[1] = pk2(cA.y, cA.y);
            wv[2] = pk2(cA.z, cA.z); wv[3] = pk2(cA.w, cA.w);
            wv[4] = pk2(cB.x, cB.x); wv[5] = pk2(cB.y, cB.y);
            wv[6] = pk2(cB.z, cB.z); wv[7] = pk2(cB.w, cB.w);
            #pragma unroll
            for (int j = 0; j < 8; j++)
                #pragma unroll
                for (int pp = 0; pp < 4; pp++)
                    acc[j][pp] = ffma2(zp[pp], wv[j], acc[j][pp]);
        }
        // argmin epilogue (ascending k, strict < -> smallest k wins ties)
        #pragma unroll
        for (int j = 0; j < 8; j++) {
            float cn2v = s_cn2[c0 + j];
            #pragma unroll
            for (int pp = 0; pp < 4; pp++) {
                float lo, hi; upk2(acc[j][pp], lo, hi);
                float e0 = cn2v - lo, e1 = cn2v - hi;
                if (e0 < best[2*pp+0]) { best[2*pp+0] = e0; bidx[2*pp+0] = c0 + j; }
                if (e1 < best[2*pp+1]) { best[2*pp+1] = e1; bidx[2*pp+1] = c0 + j; }
            }
        }
    }
    #pragma unroll
    for (int i = 0; i < 8; i++) {
        s_re[ty*128 + px0 + i] = best[i];
        s_ri[ty*128 + px0 + i] = bidx[i];
    }
    __syncthreads();

    float cl = 0.f;
    if (tid < 128) {
        const int px = tid;
        float fb = 3.4e38f; int fi = 0;
        #pragma unroll
        for (int t = 0; t < 16; t++) {      // ascending ty -> ascending k, strict <
            float e = s_re[t*128 + px];
            if (e < fb) { fb = e; fi = s_ri[t*128 + px]; }
        }
        out_idx[P0 + px] = (float)fi;
        // exact elementwise commit-loss contribution for winning code
        #pragma unroll
        for (int d = 0; d < DIM; d++) {
            float df = s_cbT[d*CBT_STRIDE + fi] - s_zT[d*128 + px];
            cl = fmaf(df, df, cl);
        }
    }
    #pragma unroll
    for (int off = 16; off; off >>= 1) cl += __shfl_down_sync(0xffffffffu, cl, off);
    __shared__ float wsum[8];
    if ((tid & 31) == 0) wsum[tid >> 5] = (tid < 128) ? cl : 0.f;
    __syncthreads();
    if (tid == 0) {
        float s = 0.f;
        #pragma unroll
        for (int w = 0; w < 4; w++) s += wsum[w];
        atomicAdd(&g_loss, (double)s);
    }
}

// ---------------------------------------------------------------------------
// k4: nearest-upsample2(h2) + conv3 (32->16, 3x3 SAME) + gelu
// single pass over all 16 oc; only 9 distinct input values per ic (up2 dup)
// grid (4, B): output tile 32x32; block (16,16); thread = 2x2 micro-tile
// ---------------------------------------------------------------------------
#define K4_SMEM ((32*18*18 + 32*9*16 + 16)*4)
__global__ __launch_bounds__(256) void k4(const float* __restrict__ w3,
                                          const float* __restrict__ b3) {
    extern __shared__ __align__(16) float sm4[];
    float* s_h = sm4;
    float* s_w = sm4 + 32*18*18;     // [ic][t][oc]
    float* s_b = s_w + 32*9*16;
    const int b = blockIdx.y;
    const int tile = blockIdx.x;
    const int oy = (tile >> 1) * 32, ox = (tile & 1) * 32;
    const int hy0 = oy/2 - 1, hx0 = ox/2 - 1;
    const int tid = threadIdx.y*16 + threadIdx.x;
    for (int i = tid; i < 16*32*9; i += 256) {
        int o = i / 288; int rem = i - o*288; int ic = rem / 9; int t = rem - ic*9;
        s_w[(ic*9 + t)*16 + o] = w3[i];
    }
    if (tid < 16) s_b[tid] = b3[tid];
    for (int i = tid; i < 32*18*18; i += 256) {
        int ic = i / 324;
        int rem = i - ic*324;
        int r = rem / 18, c = rem - r*18;
        int hy = hy0 + r, hx = hx0 + c;
        float v = 0.f;
        if ((unsigned)hy < 32u && (unsigned)hx < 32u)
            v = g_h2[((b*32+ic)*32 + hy)*32 + hx];
        s_h[i] = v;
    }
    __syncthreads();
    const int ty = threadIdx.y, tx = threadIdx.x;
    const int y0 = oy + 2*ty, x0 = ox + 2*tx;
    // distinct input rows/cols: {ty, ty+1, ty+2} x {tx, tx+1, tx+2}
    // map: index (dy+ky) or (dx+kx) in 0..3 -> {0,1,1,2}
    const int map[4] = {0, 1, 1, 2};
    u64 acc[8][4];
    #pragma unroll
    for (int op = 0; op < 8; op++)
        #pragma unroll
        for (int q = 0; q < 4; q++) acc[op][q] = 0ull;
    #pragma unroll 1
    for (int ic = 0; ic < 32; ic++) {
        u64 vp[3][3];
        #pragma unroll
        for (int a = 0; a < 3; a++)
            #pragma unroll
            for (int c = 0; c < 3; c++) {
                float v = s_h[(ic*18 + ty + a)*18 + tx + c];
                vp[a][c] = pk2(v, v);
            }
        #pragma unroll
        for (int t = 0; t < 9; t++) {
            int ky = t / 3, kx = t - ky*3;
            const float* wp = &s_w[(ic*9 + t)*16];
            ulonglong2 wA = *(const ulonglong2*)&wp[0];
            ulonglong2 wB = *(const ulonglong2*)&wp[4];
            ulonglong2 wC = *(const ulonglong2*)&wp[8];
            ulonglong2 wD = *(const ulonglong2*)&wp[12];
            u64 wv[8] = {wA.x, wA.y, wB.x, wB.y, wC.x, wC.y, wD.x, wD.y};
            #pragma unroll
            for (int op = 0; op < 8; op++)
                #pragma unroll
                for (int dy = 0; dy < 2; dy++)
                    #pragma unroll
                    for (int dx = 0; dx < 2; dx++)
                        acc[op][dy*2+dx] = ffma2(vp[map[dy+ky]][map[dx+kx]], wv[op], acc[op][dy*2+dx]);
        }
    }
    #pragma unroll
    for (int op = 0; op < 8; op++) {
        int oc = op*2;
        float blo = s_b[oc], bhi = s_b[oc+1];
        #pragma unroll
        for (int dy = 0; dy < 2; dy++)
            #pragma unroll
            for (int dx = 0; dx < 2; dx++) {
                float lo, hi;
                upk2(acc[op][dy*2+dx], lo, hi);
                g_g[((b*16+oc+0)*64 + (y0+dy))*64 + (x0+dx)] = gelu_exact(lo + blo);
                g_g[((b*16+oc+1)*64 + (y0+dy))*64 + (x0+dx)] = gelu_exact(hi + bhi);
            }
    }
}

// ---------------------------------------------------------------------------
// k5: nearest-upsample2(g) + conv4 (16->1, 3x3 SAME) + clip
// 9 distinct input values per ic; grid (16, B); block (16,16)
// ---------------------------------------------------------------------------
__global__ __launch_bounds__(256) void k5(const float* __restrict__ w4,
                                          const float* __restrict__ b4,
                                          float* __restrict__ out) {
    __shared__ float s_g[16*18*18];
    __shared__ float s_w[144];
    __shared__ float s_bb[1];
    const int b = blockIdx.y;
    const int tile = blockIdx.x;
    const int oy = (tile >> 2) * 32, ox = (tile & 3) * 32;
    const int gy0 = oy/2 - 1, gx0 = ox/2 - 1;
    const int tid = threadIdx.y*16 + threadIdx.x;
    if (tid < 144) s_w[tid] = w4[tid];
    if (tid == 0) s_bb[0] = b4[0];
    for (int i = tid; i < 16*18*18; i += 256) {
        int ic = i / 324;
        int rem = i - ic*324;
        int r = rem / 18, c = rem - r*18;
        int gy = gy0 + r, gx = gx0 + c;
        float v = 0.f;
        if ((unsigned)gy < 64u && (unsigned)gx < 64u)
            v = g_g[((b*16+ic)*64 + gy)*64 + gx];
        s_g[i] = v;
    }
    __syncthreads();
    const int ty = threadIdx.y, tx = threadIdx.x;
    const int y0 = oy + 2*ty, x0 = ox + 2*tx;
    const int map[4] = {0, 1, 1, 2};
    float acc[4] = {0.f, 0.f, 0.f, 0.f};
    #pragma unroll 1
    for (int ic = 0; ic < 16; ic++) {
        float v[3][3];
        #pragma unroll
        for (int a = 0; a < 3; a++)
            #pragma unroll
            for (int c = 0; c < 3; c++)
                v[a][c] = s_g[(ic*18 + ty + a)*18 + tx + c];
        const float* w = &s_w[ic*9];
        #pragma unroll
        for (int t = 0; t < 9; t++) {
            int ky = t / 3, kx = t - ky*3;
            float wt = w[t];
            #pragma unroll
            for (int dy = 0; dy < 2; dy++)
                #pragma unroll
                for (int dx = 0; dx < 2; dx++)
                    acc[dy*2+dx] = fmaf(wt, v[map[dy+ky]][map[dx+kx]], acc[dy*2+dx]);
        }
    }
    float bb = s_bb[0];
    #pragma unroll
    for (int dy = 0; dy < 2; dy++)
        #pragma unroll
        for (int dx = 0; dx < 2; dx++) {
            float v = fminf(fmaxf(acc[dy*2+dx] + bb, -1.f), 1.f);
            out[(b*H0 + (y0+dy))*W0 + (x0+dx)] = v;
        }
}

// ---------------------------------------------------------------------------
__global__ void k_zero() { if (threadIdx.x == 0) g_loss = 0.0; }
__global__ void k_fin(float* __restrict__ out_loss) {
    if (threadIdx.x == 0)
        out_loss[0] = (float)(g_loss / (double)(BATCH * 1024 * DIM));
}

// ---------------------------------------------------------------------------
extern "C" void kernel_launch(void* const* d_in, const int* in_sizes, int n_in,
                              void* d_out, int out_size) {
    const float* x  = (const float*)d_in[0];
    const float* w1 = (const float*)d_in[1];
    const float* b1 = (const float*)d_in[2];
    const float* w2 = (const float*)d_in[3];
    const float* b2 = (const float*)d_in[4];
    const float* cb = (const float*)d_in[5];
    const float* w3 = (const float*)d_in[6];
    const float* b3 = (const float*)d_in[7];
    const float* w4 = (const float*)d_in[8];
    const float* b4 = (const float*)d_in[9];

    float* out      = (float*)d_out;
    float* out_idx  = out + BATCH*H0*W0;          // 2,097,152
    float* out_loss = out_idx + BATCH*H2*H2;      // +131,072

    cudaFuncSetAttribute(k2, cudaFuncAttributeMaxDynamicSharedMemorySize, K2_SMEM);
    cudaFuncSetAttribute(k3, cudaFuncAttributeMaxDynamicSharedMemorySize, K3_SMEM);
    cudaFuncSetAttribute(k4, cudaFuncAttributeMaxDynamicSharedMemorySize, K4_SMEM);

    k_zero<<<1, 32>>>();
    k1<<<dim3(8, BATCH), 256>>>(x, w1, b1);
    k2<<<dim3(4, BATCH), 256, K2_SMEM>>>(w2, b2);
    k3<<<1024, 256, K3_SMEM>>>(cb, out_idx);
    k4<<<dim3(4, BATCH), dim3(16,16), K4_SMEM>>>(w3, b3);
    k5<<<dim3(16, BATCH), dim3(16,16)>>>(w4, b4, out);
    k_fin<<<1, 32>>>(out_loss);
}

// round 4
// speedup vs baseline: 1.2100x; 1.0051x over previous
#include <cuda_runtime.h>
#include <math.h>

#define BATCH 128
#define H0 128
#define W0 128
#define C1 16
#define H1 64
#define C2 32
#define H2 32
#define NCODES 512
#define DIM 32

typedef unsigned long long u64;

// Scratch (allocation-free rule: __device__ globals)
__device__ float g_h1[BATCH*C1*H1*H1];   // after conv1+pool+gelu  [B,16,64,64]
__device__ float g_h2[BATCH*C2*H2*H2];   // after conv2+pool       [B,32,32,32]
__device__ float g_g [BATCH*C1*H1*H1];   // after up+conv3+gelu    [B,16,64,64]
__device__ double g_loss;

__device__ __forceinline__ float gelu_exact(float v) {
    return 0.5f * v * (1.0f + erff(v * 0.70710678118654752440f));
}

// ---- packed fp32x2 helpers (Blackwell FFMA2 path) -------------------------
__device__ __forceinline__ u64 pk2(float lo, float hi) {
    u64 r; asm("mov.b64 %0, {%1,%2};" : "=l"(r) : "f"(lo), "f"(hi)); return r;
}
__device__ __forceinline__ void upk2(u64 v, float& lo, float& hi) {
    asm("mov.b64 {%0,%1}, %2;" : "=f"(lo), "=f"(hi) : "l"(v));
}
__device__ __forceinline__ u64 ffma2(u64 a, u64 b, u64 c) {
    u64 d; asm("fma.rn.f32x2 %0, %1, %2, %3;" : "=l"(d) : "l"(a), "l"(b), "l"(c)); return d;
}

// ---------------------------------------------------------------------------
// k1: conv1 (1->16, 3x3 SAME) + maxpool2 + gelu  (oc-paired f32x2)
// ---------------------------------------------------------------------------
__global__ __launch_bounds__(256) void k1(const float* __restrict__ x,
                                          const float* __restrict__ w1,
                                          const float* __restrict__ b1) {
    __shared__ __align__(16) float s_in[34*66];
    __shared__ __align__(16) float s_w[9*C1];     // [t][oc]
    __shared__ float s_b[C1];
    const int b = blockIdx.y;
    const int tile = blockIdx.x;
    const int px0 = (tile & 1) * 32;
    const int py0 = (tile >> 1) * 16;
    const int tid = threadIdx.x;
    if (tid < C1*9) { int oc = tid / 9, t = tid - oc*9; s_w[t*C1 + oc] = w1[tid]; }
    if (tid < C1)   s_b[tid] = b1[tid];
    const float* xim = x + b * (H0*W0);
    for (int i = tid; i < 34*66; i += 256) {
        int r = i / 66, c = i - r*66;
        int gy = 2*py0 - 1 + r;
        int gx = 2*px0 - 1 + c;
        float v = 0.f;
        if ((unsigned)gy < (unsigned)H0 && (unsigned)gx < (unsigned)W0)
            v = xim[gy*W0 + gx];
        s_in[i] = v;
    }
    __syncthreads();
    #pragma unroll 1
    for (int p = tid; p < 32*16; p += 256) {
        int py = p >> 5, px = p & 31;
        u64 up[4][4];
        #pragma unroll
        for (int i = 0; i < 4; i++) {
            float2 a = *(const float2*)&s_in[(2*py+i)*66 + 2*px];
            float2 c = *(const float2*)&s_in[(2*py+i)*66 + 2*px + 2];
            up[i][0] = pk2(a.x, a.x); up[i][1] = pk2(a.y, a.y);
            up[i][2] = pk2(c.x, c.x); up[i][3] = pk2(c.y, c.y);
        }
        u64 acc[8][4];
        #pragma unroll
        for (int op = 0; op < 8; op++)
            #pragma unroll
            for (int q = 0; q < 4; q++) acc[op][q] = 0ull;
        #pragma unroll
        for (int t = 0; t < 9; t++) {
            int ky = t / 3, kx = t - ky*3;
            ulonglong2 wA = *(const ulonglong2*)&s_w[t*C1 + 0];
            ulonglong2 wB = *(const ulonglong2*)&s_w[t*C1 + 4];
            ulonglong2 wC = *(const ulonglong2*)&s_w[t*C1 + 8];
            ulonglong2 wD = *(const ulonglong2*)&s_w[t*C1 + 12];
            u64 wv[8] = {wA.x, wA.y, wB.x, wB.y, wC.x, wC.y, wD.x, wD.y};
            #pragma unroll
            for (int op = 0; op < 8; op++)
                #pragma unroll
                for (int dy = 0; dy < 2; dy++)
                    #pragma unroll
                    for (int dx = 0; dx < 2; dx++)
                        acc[op][dy*2+dx] = ffma2(up[dy+ky][dx+kx], wv[op], acc[op][dy*2+dx]);
        }
        int gy = py0 + py, gx = px0 + px;
        #pragma unroll
        for (int op = 0; op < 8; op++) {
            float l0,h0,l1,h1,l2,h2,l3,h3;
            upk2(acc[op][0], l0, h0); upk2(acc[op][1], l1, h1);
            upk2(acc[op][2], l2, h2); upk2(acc[op][3], l3, h3);
            float mlo = fmaxf(fmaxf(l0,l1), fmaxf(l2,l3)) + s_b[op*2+0];
            float mhi = fmaxf(fmaxf(h0,h1), fmaxf(h2,h3)) + s_b[op*2+1];
            g_h1[((b*C1+op*2+0)*H1 + gy)*H1 + gx] = gelu_exact(mlo);
            g_h1[((b*C1+op*2+1)*H1 + gy)*H1 + gx] = gelu_exact(mhi);
        }
    }
}

// ---------------------------------------------------------------------------
// k2: conv2 (16->32, 3x3 SAME) + maxpool2  (oc-paired f32x2, 2 passes of 16 oc)
// ---------------------------------------------------------------------------
#define K2_SMEM ((16*18*66 + 16*9*32 + 32)*4)
__global__ __launch_bounds__(256) void k2(const float* __restrict__ w2,
                                          const float* __restrict__ b2) {
    extern __shared__ __align__(16) float sm2[];
    float* s_in = sm2;
    float* s_w  = sm2 + 16*18*66;      // [ic][t][oc]
    float* s_b  = s_w + 16*9*32;
    const int b = blockIdx.y;
    const int ry0 = blockIdx.x * 8;
    const int tid = threadIdx.x;
    for (int i = tid; i < 32*16*9; i += 256) {
        int o = i / 144; int rem = i - o*144; int ic = rem / 9; int t = rem - ic*9;
        s_w[(ic*9 + t)*32 + o] = w2[i];
    }
    if (tid < 32) s_b[tid] = b2[tid];
    for (int i = tid; i < 16*18*66; i += 256) {
        int ic = i / (18*66);
        int rem = i - ic*(18*66);
        int r = rem / 66, c = rem - r*66;
        int gy = 2*ry0 - 1 + r, gx = c - 1;
        float v = 0.f;
        if ((unsigned)gy < 64u && (unsigned)gx < 64u)
            v = g_h1[((b*16+ic)*64 + gy)*64 + gx];
        s_in[i] = v;
    }
    __syncthreads();
    const int py = tid >> 5, px = tid & 31;
    const int gy = ry0 + py, gx = px;
    #pragma unroll 1
    for (int pass = 0; pass < 2; pass++) {
        u64 acc[8][4];
        #pragma unroll
        for (int op = 0; op < 8; op++)
            #pragma unroll
            for (int q = 0; q < 4; q++) acc[op][q] = 0ull;
        #pragma unroll 1
        for (int ic = 0; ic < 16; ic++) {
            const float* base = &s_in[(ic*18 + 2*py)*66 + 2*px];
            u64 up[4][4];
            #pragma unroll
            for (int i = 0; i < 4; i++) {
                float2 a = *(const float2*)&base[i*66];
                float2 c = *(const float2*)&base[i*66 + 2];
                up[i][0] = pk2(a.x, a.x); up[i][1] = pk2(a.y, a.y);
                up[i][2] = pk2(c.x, c.x); up[i][3] = pk2(c.y, c.y);
            }
            #pragma unroll
            for (int t = 0; t < 9; t++) {
                int ky = t / 3, kx = t - ky*3;
                const float* wp = &s_w[(ic*9 + t)*32 + pass*16];
                ulonglong2 wA = *(const ulonglong2*)&wp[0];
                ulonglong2 wB = *(const ulonglong2*)&wp[4];
                ulonglong2 wC = *(const ulonglong2*)&wp[8];
                ulonglong2 wD = *(const ulonglong2*)&wp[12];
                u64 wv[8] = {wA.x, wA.y, wB.x, wB.y, wC.x, wC.y, wD.x, wD.y};
                #pragma unroll
                for (int op = 0; op < 8; op++)
                    #pragma unroll
                    for (int dy = 0; dy < 2; dy++)
                        #pragma unroll
                        for (int dx = 0; dx < 2; dx++)
                            acc[op][dy*2+dx] = ffma2(up[dy+ky][dx+kx], wv[op], acc[op][dy*2+dx]);
            }
        }
        #pragma unroll
        for (int op = 0; op < 8; op++) {
            float l0,h0,l1,h1,l2,h2,l3,h3;
            upk2(acc[op][0], l0, h0); upk2(acc[op][1], l1, h1);
            upk2(acc[op][2], l2, h2); upk2(acc[op][3], l3, h3);
            int oc = pass*16 + op*2;
            float mlo = fmaxf(fmaxf(l0,l1), fmaxf(l2,l3)) + s_b[oc+0];
            float mhi = fmaxf(fmaxf(h0,h1), fmaxf(h2,h3)) + s_b[oc+1];
            g_h2[((b*32+oc+0)*32 + gy)*32 + gx] = mlo;
            g_h2[((b*32+oc+1)*32 + gy)*32 + gx] = mhi;
        }
    }
}

// ---------------------------------------------------------------------------
// k3: VQ GEMM with lane-dedup mapping.
// block = 128 px x 512 codes (4 passes of 128 codes), 256 threads.
// warp lanes: pg = lane&7 (8 px-groups, 8px each), cg = lane>>3 (4 code-groups)
// warp w: pxhalf = w&1 (64 px), strip = w>>1 (32 codes per pass)
// => z LDS.128: 8 distinct addrs = 1 wavefront; cb LDS.128: 4 distinct = 1 wf.
// comparator e' = cn/2 - dot (zz const per px); final reduce ties on index.
// ---------------------------------------------------------------------------
#define CBT_STRIDE 516
#define K3_SMEM ((32*CBT_STRIDE + 32*128 + 512 + 16*128*2)*4)
__global__ __launch_bounds__(256, 2) void k3(const float* __restrict__ codebook,
                                             float* __restrict__ out_idx) {
    extern __shared__ __align__(16) float sm3[];
    float* s_cbT = sm3;                         // [32][516]
    float* s_zT  = s_cbT + 32*CBT_STRIDE;       // [32][128]
    float* s_cn2 = s_zT + 32*128;               // [512]
    float* s_re  = s_cn2 + 512;                 // [16 slots][128 px]
    int*   s_ri  = (int*)(s_re + 16*128);       // [16][128]
    const int tid = threadIdx.x;
    const int P0 = blockIdx.x * 128;            // 128 px, same image
    const int b  = P0 >> 10;
    const int n0 = P0 & 1023;

    // stage codebook transposed + z transposed
    for (int i = tid; i < NCODES*DIM; i += 256) {
        int k = i >> 5, d = i & 31;
        s_cbT[d*CBT_STRIDE + k] = codebook[i];
    }
    for (int i = tid; i < 32*128; i += 256) {
        int d = i >> 7, px = i & 127;
        s_zT[d*128 + px] = g_h2[(b*C2 + d)*1024 + n0 + px];
    }
    __syncthreads();
    for (int k = tid; k < NCODES; k += 256) {
        float s = 0.f;
        #pragma unroll
        for (int d = 0; d < DIM; d++) {
            float c = s_cbT[d*CBT_STRIDE + k];
            s = fmaf(c, c, s);
        }
        s_cn2[k] = 0.5f * s;
    }
    __syncthreads();

    const int lane = tid & 31, w = tid >> 5;
    const int pg = lane & 7, cg = lane >> 3;
    const int pxhalf = w & 1, strip = w >> 1;
    const int px0 = pxhalf*64 + pg*8;
    const int slot = strip*4 + cg;

    float best[8]; int bidx[8];
    #pragma unroll
    for (int i = 0; i < 8; i++) { best[i] = 3.4e38f; bidx[i] = 0; }

    #pragma unroll 1
    for (int pass = 0; pass < 4; pass++) {
        const int c0 = pass*128 + strip*32 + cg*8;
        u64 acc[8][4];
        #pragma unroll
        for (int j = 0; j < 8; j++)
            #pragma unroll
            for (int pp = 0; pp < 4; pp++) acc[j][pp] = 0ull;
        #pragma unroll 4
        for (int d = 0; d < 32; d++) {
            const float* zr = &s_zT[d*128 + px0];
            ulonglong2 za = *(const ulonglong2*)zr;          // px 0-3 packed pairs
            ulonglong2 zb = *(const ulonglong2*)(zr + 4);    // px 4-7
            u64 zp[4] = {za.x, za.y, zb.x, zb.y};
            const float* cr = &s_cbT[d*CBT_STRIDE + c0];
            float4 cA = *(const float4*)cr;
            float4 cB = *(const float4*)(cr + 4);
            u64 wv[8];
            wv[0] = pk2(cA.x, cA.x); wv[1] = pk2(cA.y, cA.y);
            wv[2] = pk2(cA.z, cA.z); wv[3] = pk2(cA.w, cA.w);
            wv[4] = pk2(cB.x, cB.x); wv[5] = pk2(cB.y, cB.y);
            wv[6] = pk2(cB.z, cB.z); wv[7] = pk2(cB.w, cB.w);
            #pragma unroll
            for (int j = 0; j < 8; j++)
                #pragma unroll
                for (int pp = 0; pp < 4; pp++)
                    acc[j][pp] = ffma2(zp[pp], wv[j], acc[j][pp]);
        }
        // per-thread argmin over this pass's 8 codes (ascending k, strict <)
        #pragma unroll
        for (int j = 0; j < 8; j++) {
            float cn2v = s_cn2[c0 + j];
            #pragma unroll
            for (int pp = 0; pp < 4; pp++) {
                float lo, hi; upk2(acc[j][pp], lo, hi);
                float e0 = cn2v - lo, e1 = cn2v - hi;
                if (e0 < best[2*pp+0]) { best[2*pp+0] = e0; bidx[2*pp+0] = c0 + j; }
                if (e1 < best[2*pp+1]) { best[2*pp+1] = e1; bidx[2*pp+1] = c0 + j; }
            }
        }
    }
    #pragma unroll
    for (int i = 0; i < 8; i++) {
        s_re[slot*128 + px0 + i] = best[i];
        s_ri[slot*128 + px0 + i] = bidx[i];
    }
    __syncthreads();

    float cl = 0.f;
    if (tid < 128) {
        const int px = tid;
        float fb = 3.4e38f; int fi = 0x7fffffff;
        #pragma unroll
        for (int t = 0; t < 16; t++) {   // tie-break on smaller code index: exact argmin
            float e = s_re[t*128 + px];
            int   i = s_ri[t*128 + px];
            if (e < fb || (e == fb && i < fi)) { fb = e; fi = i; }
        }
        out_idx[P0 + px] = (float)fi;
        // exact elementwise commit-loss contribution for winning code
        #pragma unroll
        for (int d = 0; d < DIM; d++) {
            float df = s_cbT[d*CBT_STRIDE + fi] - s_zT[d*128 + px];
            cl = fmaf(df, df, cl);
        }
    }
    #pragma unroll
    for (int off = 16; off; off >>= 1) cl += __shfl_down_sync(0xffffffffu, cl, off);
    __shared__ float wsum[8];
    if ((tid & 31) == 0) wsum[tid >> 5] = (tid < 128) ? cl : 0.f;
    __syncthreads();
    if (tid == 0) {
        float s = 0.f;
        #pragma unroll
        for (int w2_ = 0; w2_ < 4; w2_++) s += wsum[w2_];
        atomicAdd(&g_loss, (double)s);
    }
}

// ---------------------------------------------------------------------------
// k4: nearest-upsample2(h2) + conv3 (32->16, 3x3 SAME) + gelu
// ---------------------------------------------------------------------------
#define K4_SMEM ((32*18*18 + 32*9*16 + 16)*4)
__global__ __launch_bounds__(256) void k4(const float* __restrict__ w3,
                                          const float* __restrict__ b3) {
    extern __shared__ __align__(16) float sm4[];
    float* s_h = sm4;
    float* s_w = sm4 + 32*18*18;     // [ic][t][oc]
    float* s_b = s_w + 32*9*16;
    const int b = blockIdx.y;
    const int tile = blockIdx.x;
    const int oy = (tile >> 1) * 32, ox = (tile & 1) * 32;
    const int hy0 = oy/2 - 1, hx0 = ox/2 - 1;
    const int tid = threadIdx.y*16 + threadIdx.x;
    for (int i = tid; i < 16*32*9; i += 256) {
        int o = i / 288; int rem = i - o*288; int ic = rem / 9; int t = rem - ic*9;
        s_w[(ic*9 + t)*16 + o] = w3[i];
    }
    if (tid < 16) s_b[tid] = b3[tid];
    for (int i = tid; i < 32*18*18; i += 256) {
        int ic = i / 324;
        int rem = i - ic*324;
        int r = rem / 18, c = rem - r*18;
        int hy = hy0 + r, hx = hx0 + c;
        float v = 0.f;
        if ((unsigned)hy < 32u && (unsigned)hx < 32u)
            v = g_h2[((b*32+ic)*32 + hy)*32 + hx];
        s_h[i] = v;
    }
    __syncthreads();
    const int ty = threadIdx.y, tx = threadIdx.x;
    const int y0 = oy + 2*ty, x0 = ox + 2*tx;
    const int map[4] = {0, 1, 1, 2};
    u64 acc[8][4];
    #pragma unroll
    for (int op = 0; op < 8; op++)
        #pragma unroll
        for (int q = 0; q < 4; q++) acc[op][q] = 0ull;
    #pragma unroll 1
    for (int ic = 0; ic < 32; ic++) {
        u64 vp[3][3];
        #pragma unroll
        for (int a = 0; a < 3; a++)
            #pragma unroll
            for (int c = 0; c < 3; c++) {
                float v = s_h[(ic*18 + ty + a)*18 + tx + c];
                vp[a][c] = pk2(v, v);
            }
        #pragma unroll
        for (int t = 0; t < 9; t++) {
            int ky = t / 3, kx = t - ky*3;
            const float* wp = &s_w[(ic*9 + t)*16];
            ulonglong2 wA = *(const ulonglong2*)&wp[0];
            ulonglong2 wB = *(const ulonglong2*)&wp[4];
            ulonglong2 wC = *(const ulonglong2*)&wp[8];
            ulonglong2 wD = *(const ulonglong2*)&wp[12];
            u64 wv[8] = {wA.x, wA.y, wB.x, wB.y, wC.x, wC.y, wD.x, wD.y};
            #pragma unroll
            for (int op = 0; op < 8; op++)
                #pragma unroll
                for (int dy = 0; dy < 2; dy++)
                    #pragma unroll
                    for (int dx = 0; dx < 2; dx++)
                        acc[op][dy*2+dx] = ffma2(vp[map[dy+ky]][map[dx+kx]], wv[op], acc[op][dy*2+dx]);
        }
    }
    #pragma unroll
    for (int op = 0; op < 8; op++) {
        int oc = op*2;
        float blo = s_b[oc], bhi = s_b[oc+1];
        #pragma unroll
        for (int dy = 0; dy < 2; dy++)
            #pragma unroll
            for (int dx = 0; dx < 2; dx++) {
                float lo, hi;
                upk2(acc[op][dy*2+dx], lo, hi);
                g_g[((b*16+oc+0)*64 + (y0+dy))*64 + (x0+dx)] = gelu_exact(lo + blo);
                g_g[((b*16+oc+1)*64 + (y0+dy))*64 + (x0+dx)] = gelu_exact(hi + bhi);
            }
    }
}

// ---------------------------------------------------------------------------
// k5: nearest-upsample2(g) + conv4 (16->1, 3x3 SAME) + clip
// ---------------------------------------------------------------------------
__global__ __launch_bounds__(256) void k5(const float* __restrict__ w4,
                                          const float* __restrict__ b4,
                                          float* __restrict__ out) {
    __shared__ float s_g[16*18*18];
    __shared__ float s_w[144];
    __shared__ float s_bb[1];
    const int b = blockIdx.y;
    const int tile = blockIdx.x;
    const int oy = (tile >> 2) * 32, ox = (tile & 3) * 32;
    const int gy0 = oy/2 - 1, gx0 = ox/2 - 1;
    const int tid = threadIdx.y*16 + threadIdx.x;
    if (tid < 144) s_w[tid] = w4[tid];
    if (tid == 0) s_bb[0] = b4[0];
    for (int i = tid; i < 16*18*18; i += 256) {
        int ic = i / 324;
        int rem = i - ic*324;
        int r = rem / 18, c = rem - r*18;
        int gy = gy0 + r, gx = gx0 + c;
        float v = 0.f;
        if ((unsigned)gy < 64u && (unsigned)gx < 64u)
            v = g_g[((b*16+ic)*64 + gy)*64 + gx];
        s_g[i] = v;
    }
    __syncthreads();
    const int ty = threadIdx.y, tx = threadIdx.x;
    const int y0 = oy + 2*ty, x0 = ox + 2*tx;
    const int map[4] = {0, 1, 1, 2};
    float acc[4] = {0.f, 0.f, 0.f, 0.f};
    #pragma unroll 1
    for (int ic = 0; ic < 16; ic++) {
        float v[3][3];
        #pragma unroll
        for (int a = 0; a < 3; a++)
            #pragma unroll
            for (int c = 0; c < 3; c++)
                v[a][c] = s_g[(ic*18 + ty + a)*18 + tx + c];
        const float* w = &s_w[ic*9];
        #pragma unroll
        for (int t = 0; t < 9; t++) {
            int ky = t / 3, kx = t - ky*3;
            float wt = w[t];
            #pragma unroll
            for (int dy = 0; dy < 2; dy++)
                #pragma unroll
                for (int dx = 0; dx < 2; dx++)
                    acc[dy*2+dx] = fmaf(wt, v[map[dy+ky]][map[dx+kx]], acc[dy*2+dx]);
        }
    }
    float bb = s_bb[0];
    #pragma unroll
    for (int dy = 0; dy < 2; dy++)
        #pragma unroll
        for (int dx = 0; dx < 2; dx++) {
            float v = fminf(fmaxf(acc[dy*2+dx] + bb, -1.f), 1.f);
            out[(b*H0 + (y0+dy))*W0 + (x0+dx)] = v;
        }
}

// ---------------------------------------------------------------------------
__global__ void k_zero() { if (threadIdx.x == 0) g_loss = 0.0; }
__global__ void k_fin(float* __restrict__ out_loss) {
    if (threadIdx.x == 0)
        out_loss[0] = (float)(g_loss / (double)(BATCH * 1024 * DIM));
}

// ---------------------------------------------------------------------------
extern "C" void kernel_launch(void* const* d_in, const int* in_sizes, int n_in,
                              void* d_out, int out_size) {
    const float* x  = (const float*)d_in[0];
    const float* w1 = (const float*)d_in[1];
    const float* b1 = (const float*)d_in[2];
    const float* w2 = (const float*)d_in[3];
    const float* b2 = (const float*)d_in[4];
    const float* cb = (const float*)d_in[5];
    const float* w3 = (const float*)d_in[6];
    const float* b3 = (const float*)d_in[7];
    const float* w4 = (const float*)d_in[8];
    const float* b4 = (const float*)d_in[9];

    float* out      = (float*)d_out;
    float* out_idx  = out + BATCH*H0*W0;          // 2,097,152
    float* out_loss = out_idx + BATCH*H2*H2;      // +131,072

    cudaFuncSetAttribute(k2, cudaFuncAttributeMaxDynamicSharedMemorySize, K2_SMEM);
    cudaFuncSetAttribute(k3, cudaFuncAttributeMaxDynamicSharedMemorySize, K3_SMEM);
    cudaFuncSetAttribute(k4, cudaFuncAttributeMaxDynamicSharedMemorySize, K4_SMEM);

    k_zero<<<1, 32>>>();
    k1<<<dim3(8, BATCH), 256>>>(x, w1, b1);
    k2<<<dim3(4, BATCH), 256, K2_SMEM>>>(w2, b2);
    k3<<<1024, 256, K3_SMEM>>>(cb, out_idx);
    k4<<<dim3(4, BATCH), dim3(16,16), K4_SMEM>>>(w3, b3);
    k5<<<dim3(16, BATCH), dim3(16,16)>>>(w4, b4, out);
    k_fin<<<1, 32>>>(out_loss);
}

// round 5
// speedup vs baseline: 1.2208x; 1.0090x over previous
#include <cuda_runtime.h>
#include <math.h>

#define BATCH 128
#define H0 128
#define W0 128
#define C1 16
#define H1 64
#define C2 32
#define H2 32
#define NCODES 512
#define DIM 32

typedef unsigned long long u64;

// Scratch (allocation-free rule: __device__ globals)
__device__ float g_h1[BATCH*C1*H1*H1];   // after conv1+pool+gelu  [B,16,64,64]
__device__ float g_h2[BATCH*C2*H2*H2];   // after conv2+pool       [B,32,32,32]
__device__ float g_g [BATCH*C1*H1*H1];   // after up+conv3+gelu    [B,16,64,64]
__device__ double g_loss;

__device__ __forceinline__ float gelu_exact(float v) {
    return 0.5f * v * (1.0f + erff(v * 0.70710678118654752440f));
}

// ---- packed fp32x2 helpers (Blackwell FFMA2 path) -------------------------
__device__ __forceinline__ u64 pk2(float lo, float hi) {
    u64 r; asm("mov.b64 %0, {%1,%2};" : "=l"(r) : "f"(lo), "f"(hi)); return r;
}
__device__ __forceinline__ void upk2(u64 v, float& lo, float& hi) {
    asm("mov.b64 {%0,%1}, %2;" : "=f"(lo), "=f"(hi) : "l"(v));
}
__device__ __forceinline__ u64 ffma2(u64 a, u64 b, u64 c) {
    u64 d; asm("fma.rn.f32x2 %0, %1, %2, %3;" : "=l"(d) : "l"(a), "l"(b), "l"(c)); return d;
}

// ---------------------------------------------------------------------------
// k1: conv1 (1->16, 3x3 SAME) + maxpool2 + gelu  (oc-paired f32x2)
// ---------------------------------------------------------------------------
__global__ __launch_bounds__(256) void k1(const float* __restrict__ x,
                                          const float* __restrict__ w1,
                                          const float* __restrict__ b1) {
    __shared__ __align__(16) float s_in[34*66];
    __shared__ __align__(16) float s_w[9*C1];     // [t][oc]
    __shared__ float s_b[C1];
    const int b = blockIdx.y;
    const int tile = blockIdx.x;
    const int px0 = (tile & 1) * 32;
    const int py0 = (tile >> 1) * 16;
    const int tid = threadIdx.x;
    if (tid < C1*9) { int oc = tid / 9, t = tid - oc*9; s_w[t*C1 + oc] = w1[tid]; }
    if (tid < C1)   s_b[tid] = b1[tid];
    const float* xim = x + b * (H0*W0);
    for (int i = tid; i < 34*66; i += 256) {
        int r = i / 66, c = i - r*66;
        int gy = 2*py0 - 1 + r;
        int gx = 2*px0 - 1 + c;
        float v = 0.f;
        if ((unsigned)gy < (unsigned)H0 && (unsigned)gx < (unsigned)W0)
            v = xim[gy*W0 + gx];
        s_in[i] = v;
    }
    __syncthreads();
    #pragma unroll 1
    for (int p = tid; p < 32*16; p += 256) {
        int py = p >> 5, px = p & 31;
        u64 up[4][4];
        #pragma unroll
        for (int i = 0; i < 4; i++) {
            float2 a = *(const float2*)&s_in[(2*py+i)*66 + 2*px];
            float2 c = *(const float2*)&s_in[(2*py+i)*66 + 2*px + 2];
            up[i][0] = pk2(a.x, a.x); up[i][1] = pk2(a.y, a.y);
            up[i][2] = pk2(c.x, c.x); up[i][3] = pk2(c.y, c.y);
        }
        u64 acc[8][4];
        #pragma unroll
        for (int op = 0; op < 8; op++)
            #pragma unroll
            for (int q = 0; q < 4; q++) acc[op][q] = 0ull;
        #pragma unroll
        for (int t = 0; t < 9; t++) {
            int ky = t / 3, kx = t - ky*3;
            ulonglong2 wA = *(const ulonglong2*)&s_w[t*C1 + 0];
            ulonglong2 wB = *(const ulonglong2*)&s_w[t*C1 + 4];
            ulonglong2 wC = *(const ulonglong2*)&s_w[t*C1 + 8];
            ulonglong2 wD = *(const ulonglong2*)&s_w[t*C1 + 12];
            u64 wv[8] = {wA.x, wA.y, wB.x, wB.y, wC.x, wC.y, wD.x, wD.y};
            #pragma unroll
            for (int op = 0; op < 8; op++)
                #pragma unroll
                for (int dy = 0; dy < 2; dy++)
                    #pragma unroll
                    for (int dx = 0; dx < 2; dx++)
                        acc[op][dy*2+dx] = ffma2(up[dy+ky][dx+kx], wv[op], acc[op][dy*2+dx]);
        }
        int gy = py0 + py, gx = px0 + px;
        #pragma unroll
        for (int op = 0; op < 8; op++) {
            float l0,h0,l1,h1,l2,h2,l3,h3;
            upk2(acc[op][0], l0, h0); upk2(acc[op][1], l1, h1);
            upk2(acc[op][2], l2, h2); upk2(acc[op][3], l3, h3);
            float mlo = fmaxf(fmaxf(l0,l1), fmaxf(l2,l3)) + s_b[op*2+0];
            float mhi = fmaxf(fmaxf(h0,h1), fmaxf(h2,h3)) + s_b[op*2+1];
            g_h1[((b*C1+op*2+0)*H1 + gy)*H1 + gx] = gelu_exact(mlo);
            g_h1[((b*C1+op*2+1)*H1 + gy)*H1 + gx] = gelu_exact(mhi);
        }
    }
}

// ---------------------------------------------------------------------------
// k2: conv2 (16->32, 3x3 SAME) + maxpool2  (oc-paired f32x2, 2 passes of 16 oc)
// ---------------------------------------------------------------------------
#define K2_SMEM ((16*18*66 + 16*9*32 + 32)*4)
__global__ __launch_bounds__(256) void k2(const float* __restrict__ w2,
                                          const float* __restrict__ b2) {
    extern __shared__ __align__(16) float sm2[];
    float* s_in = sm2;
    float* s_w  = sm2 + 16*18*66;      // [ic][t][oc]
    float* s_b  = s_w + 16*9*32;
    const int b = blockIdx.y;
    const int ry0 = blockIdx.x * 8;
    const int tid = threadIdx.x;
    for (int i = tid; i < 32*16*9; i += 256) {
        int o = i / 144; int rem = i - o*144; int ic = rem / 9; int t = rem - ic*9;
        s_w[(ic*9 + t)*32 + o] = w2[i];
    }
    if (tid < 32) s_b[tid] = b2[tid];
    for (int i = tid; i < 16*18*66; i += 256) {
        int ic = i / (18*66);
        int rem = i - ic*(18*66);
        int r = rem / 66, c = rem - r*66;
        int gy = 2*ry0 - 1 + r, gx = c - 1;
        float v = 0.f;
        if ((unsigned)gy < 64u && (unsigned)gx < 64u)
            v = g_h1[((b*16+ic)*64 + gy)*64 + gx];
        s_in[i] = v;
    }
    __syncthreads();
    const int py = tid >> 5, px = tid & 31;
    const int gy = ry0 + py, gx = px;
    #pragma unroll 1
    for (int pass = 0; pass < 2; pass++) {
        u64 acc[8][4];
        #pragma unroll
        for (int op = 0; op < 8; op++)
            #pragma unroll
            for (int q = 0; q < 4; q++) acc[op][q] = 0ull;
        #pragma unroll 1
        for (int ic = 0; ic < 16; ic++) {
            const float* base = &s_in[(ic*18 + 2*py)*66 + 2*px];
            u64 up[4][4];
            #pragma unroll
            for (int i = 0; i < 4; i++) {
                float2 a = *(const float2*)&base[i*66];
                float2 c = *(const float2*)&base[i*66 + 2];
                up[i][0] = pk2(a.x, a.x); up[i][1] = pk2(a.y, a.y);
                up[i][2] = pk2(c.x, c.x); up[i][3] = pk2(c.y, c.y);
            }
            #pragma unroll
            for (int t = 0; t < 9; t++) {
                int ky = t / 3, kx = t - ky*3;
                const float* wp = &s_w[(ic*9 + t)*32 + pass*16];
                ulonglong2 wA = *(const ulonglong2*)&wp[0];
                ulonglong2 wB = *(const ulonglong2*)&wp[4];
                ulonglong2 wC = *(const ulonglong2*)&wp[8];
                ulonglong2 wD = *(const ulonglong2*)&wp[12];
                u64 wv[8] = {wA.x, wA.y, wB.x, wB.y, wC.x, wC.y, wD.x, wD.y};
                #pragma unroll
                for (int op = 0; op < 8; op++)
                    #pragma unroll
                    for (int dy = 0; dy < 2; dy++)
                        #pragma unroll
                        for (int dx = 0; dx < 2; dx++)
                            acc[op][dy*2+dx] = ffma2(up[dy+ky][dx+kx], wv[op], acc[op][dy*2+dx]);
            }
        }
        #pragma unroll
        for (int op = 0; op < 8; op++) {
            float l0,h0,l1,h1,l2,h2,l3,h3;
            upk2(acc[op][0], l0, h0); upk2(acc[op][1], l1, h1);
            upk2(acc[op][2], l2, h2); upk2(acc[op][3], l3, h3);
            int oc = pass*16 + op*2;
            float mlo = fmaxf(fmaxf(l0,l1), fmaxf(l2,l3)) + s_b[oc+0];
            float mhi = fmaxf(fmaxf(h0,h1), fmaxf(h2,h3)) + s_b[oc+1];
            g_h2[((b*32+oc+0)*32 + gy)*32 + gx] = mlo;
            g_h2[((b*32+oc+1)*32 + gy)*32 + gx] = mhi;
        }
    }
}

// ---------------------------------------------------------------------------
// k3: VQ GEMM (same as R4 — near its scalar-pipe floor; now overlapped with k4/k5)
// ---------------------------------------------------------------------------
#define CBT_STRIDE 516
#define K3_SMEM ((32*CBT_STRIDE + 32*128 + 512 + 16*128*2)*4)
__global__ __launch_bounds__(256, 2) void k3(const float* __restrict__ codebook,
                                             float* __restrict__ out_idx) {
    extern __shared__ __align__(16) float sm3[];
    float* s_cbT = sm3;                         // [32][516]
    float* s_zT  = s_cbT + 32*CBT_STRIDE;       // [32][128]
    float* s_cn2 = s_zT + 32*128;               // [512]
    float* s_re  = s_cn2 + 512;                 // [16 slots][128 px]
    int*   s_ri  = (int*)(s_re + 16*128);       // [16][128]
    const int tid = threadIdx.x;
    const int P0 = blockIdx.x * 128;
    const int b  = P0 >> 10;
    const int n0 = P0 & 1023;

    for (int i = tid; i < NCODES*DIM; i += 256) {
        int k = i >> 5, d = i & 31;
        s_cbT[d*CBT_STRIDE + k] = codebook[i];
    }
    for (int i = tid; i < 32*128; i += 256) {
        int d = i >> 7, px = i & 127;
        s_zT[d*128 + px] = g_h2[(b*C2 + d)*1024 + n0 + px];
    }
    __syncthreads();
    for (int k = tid; k < NCODES; k += 256) {
        float s = 0.f;
        #pragma unroll
        for (int d = 0; d < DIM; d++) {
            float c = s_cbT[d*CBT_STRIDE + k];
            s = fmaf(c, c, s);
        }
        s_cn2[k] = 0.5f * s;
    }
    __syncthreads();

    const int lane = tid & 31, w = tid >> 5;
    const int pg = lane & 7, cg = lane >> 3;
    const int pxhalf = w & 1, strip = w >> 1;
    const int px0 = pxhalf*64 + pg*8;
    const int slot = strip*4 + cg;

    float best[8]; int bidx[8];
    #pragma unroll
    for (int i = 0; i < 8; i++) { best[i] = 3.4e38f; bidx[i] = 0; }

    #pragma unroll 1
    for (int pass = 0; pass < 4; pass++) {
        const int c0 = pass*128 + strip*32 + cg*8;
        u64 acc[8][4];
        #pragma unroll
        for (int j = 0; j < 8; j++)
            #pragma unroll
            for (int pp = 0; pp < 4; pp++) acc[j][pp] = 0ull;
        #pragma unroll 4
        for (int d = 0; d < 32; d++) {
            const float* zr = &s_zT[d*128 + px0];
            ulonglong2 za = *(const ulonglong2*)zr;
            ulonglong2 zb = *(const ulonglong2*)(zr + 4);
            u64 zp[4] = {za.x, za.y, zb.x, zb.y};
            const float* cr = &s_cbT[d*CBT_STRIDE + c0];
            float4 cA = *(const float4*)cr;
            float4 cB = *(const float4*)(cr + 4);
            u64 wv[8];
            wv[0] = pk2(cA.x, cA.x); wv[1] = pk2(cA.y, cA.y);
            wv[2] = pk2(cA.z, cA.z); wv[3] = pk2(cA.w, cA.w);
            wv[4] = pk2(cB.x, cB.x); wv[5] = pk2(cB.y, cB.y);
            wv[6] = pk2(cB.z, cB.z); wv[7] = pk2(cB.w, cB.w);
            #pragma unroll
            for (int j = 0; j < 8; j++)
                #pragma unroll
                for (int pp = 0; pp < 4; pp++)
                    acc[j][pp] = ffma2(zp[pp], wv[j], acc[j][pp]);
        }
        #pragma unroll
        for (int j = 0; j < 8; j++) {
            float cn2v = s_cn2[c0 + j];
            #pragma unroll
            for (int pp = 0; pp < 4; pp++) {
                float lo, hi; upk2(acc[j][pp], lo, hi);
                float e0 = cn2v - lo, e1 = cn2v - hi;
                if (e0 < best[2*pp+0]) { best[2*pp+0] = e0; bidx[2*pp+0] = c0 + j; }
                if (e1 < best[2*pp+1]) { best[2*pp+1] = e1; bidx[2*pp+1] = c0 + j; }
            }
        }
    }
    #pragma unroll
    for (int i = 0; i < 8; i++) {
        s_re[slot*128 + px0 + i] = best[i];
        s_ri[slot*128 + px0 + i] = bidx[i];
    }
    __syncthreads();

    float cl = 0.f;
    if (tid < 128) {
        const int px = tid;
        float fb = 3.4e38f; int fi = 0x7fffffff;
        #pragma unroll
        for (int t = 0; t < 16; t++) {
            float e = s_re[t*128 + px];
            int   i = s_ri[t*128 + px];
            if (e < fb || (e == fb && i < fi)) { fb = e; fi = i; }
        }
        out_idx[P0 + px] = (float)fi;
        #pragma unroll
        for (int d = 0; d < DIM; d++) {
            float df = s_cbT[d*CBT_STRIDE + fi] - s_zT[d*128 + px];
            cl = fmaf(df, df, cl);
        }
    }
    #pragma unroll
    for (int off = 16; off; off >>= 1) cl += __shfl_down_sync(0xffffffffu, cl, off);
    __shared__ float wsum[8];
    if ((tid & 31) == 0) wsum[tid >> 5] = (tid < 128) ? cl : 0.f;
    __syncthreads();
    if (tid == 0) {
        float s = 0.f;
        #pragma unroll
        for (int w2_ = 0; w2_ < 4; w2_++) s += wsum[w2_];
        atomicAdd(&g_loss, (double)s);
    }
}

// ---------------------------------------------------------------------------
// k4: nearest-upsample2(h2) + conv3 (32->16, 3x3 SAME) + gelu
// ---------------------------------------------------------------------------
#define K4_SMEM ((32*18*18 + 32*9*16 + 16)*4)
__global__ __launch_bounds__(256) void k4(const float* __restrict__ w3,
                                          const float* __restrict__ b3) {
    extern __shared__ __align__(16) float sm4[];
    float* s_h = sm4;
    float* s_w = sm4 + 32*18*18;     // [ic][t][oc]
    float* s_b = s_w + 32*9*16;
    const int b = blockIdx.y;
    const int tile = blockIdx.x;
    const int oy = (tile >> 1) * 32, ox = (tile & 1) * 32;
    const int hy0 = oy/2 - 1, hx0 = ox/2 - 1;
    const int tid = threadIdx.y*16 + threadIdx.x;
    for (int i = tid; i < 16*32*9; i += 256) {
        int o = i / 288; int rem = i - o*288; int ic = rem / 9; int t = rem - ic*9;
        s_w[(ic*9 + t)*16 + o] = w3[i];
    }
    if (tid < 16) s_b[tid] = b3[tid];
    for (int i = tid; i < 32*18*18; i += 256) {
        int ic = i / 324;
        int rem = i - ic*324;
        int r = rem / 18, c = rem - r*18;
        int hy = hy0 + r, hx = hx0 + c;
        float v = 0.f;
        if ((unsigned)hy < 32u && (unsigned)hx < 32u)
            v = g_h2[((b*32+ic)*32 + hy)*32 + hx];
        s_h[i] = v;
    }
    __syncthreads();
    const int ty = threadIdx.y, tx = threadIdx.x;
    const int y0 = oy + 2*ty, x0 = ox + 2*tx;
    const int map[4] = {0, 1, 1, 2};
    u64 acc[8][4];
    #pragma unroll
    for (int op = 0; op < 8; op++)
        #pragma unroll
        for (int q = 0; q < 4; q++) acc[op][q] = 0ull;
    #pragma unroll 1
    for (int ic = 0; ic < 32; ic++) {
        u64 vp[3][3];
        #pragma unroll
        for (int a = 0; a < 3; a++)
            #pragma unroll
            for (int c = 0; c < 3; c++) {
                float v = s_h[(ic*18 + ty + a)*18 + tx + c];
                vp[a][c] = pk2(v, v);
            }
        #pragma unroll
        for (int t = 0; t < 9; t++) {
            int ky = t / 3, kx = t - ky*3;
            const float* wp = &s_w[(ic*9 + t)*16];
            ulonglong2 wA = *(const ulonglong2*)&wp[0];
            ulonglong2 wB = *(const ulonglong2*)&wp[4];
            ulonglong2 wC = *(const ulonglong2*)&wp[8];
            ulonglong2 wD = *(const ulonglong2*)&wp[12];
            u64 wv[8] = {wA.x, wA.y, wB.x, wB.y, wC.x, wC.y, wD.x, wD.y};
            #pragma unroll
            for (int op = 0; op < 8; op++)
                #pragma unroll
                for (int dy = 0; dy < 2; dy++)
                    #pragma unroll
                    for (int dx = 0; dx < 2; dx++)
                        acc[op][dy*2+dx] = ffma2(vp[map[dy+ky]][map[dx+kx]], wv[op], acc[op][dy*2+dx]);
        }
    }
    #pragma unroll
    for (int op = 0; op < 8; op++) {
        int oc = op*2;
        float blo = s_b[oc], bhi = s_b[oc+1];
        #pragma unroll
        for (int dy = 0; dy < 2; dy++)
            #pragma unroll
            for (int dx = 0; dx < 2; dx++) {
                float lo, hi;
                upk2(acc[op][dy*2+dx], lo, hi);
                g_g[((b*16+oc+0)*64 + (y0+dy))*64 + (x0+dx)] = gelu_exact(lo + blo);
                g_g[((b*16+oc+1)*64 + (y0+dy))*64 + (x0+dx)] = gelu_exact(hi + bhi);
            }
    }
}

// ---------------------------------------------------------------------------
// k5: nearest-upsample2(g) + conv4 (16->1, 3x3 SAME) + clip
// ---------------------------------------------------------------------------
__global__ __launch_bounds__(256) void k5(const float* __restrict__ w4,
                                          const float* __restrict__ b4,
                                          float* __restrict__ out) {
    __shared__ float s_g[16*18*18];
    __shared__ float s_w[144];
    __shared__ float s_bb[1];
    const int b = blockIdx.y;
    const int tile = blockIdx.x;
    const int oy = (tile >> 2) * 32, ox = (tile & 3) * 32;
    const int gy0 = oy/2 - 1, gx0 = ox/2 - 1;
    const int tid = threadIdx.y*16 + threadIdx.x;
    if (tid < 144) s_w[tid] = w4[tid];
    if (tid == 0) s_bb[0] = b4[0];
    for (int i = tid; i < 16*18*18; i += 256) {
        int ic = i / 324;
        int rem = i - ic*324;
        int r = rem / 18, c = rem - r*18;
        int gy = gy0 + r, gx = gx0 + c;
        float v = 0.f;
        if ((unsigned)gy < 64u && (unsigned)gx < 64u)
            v = g_g[((b*16+ic)*64 + gy)*64 + gx];
        s_g[i] = v;
    }
    __syncthreads();
    const int ty = threadIdx.y, tx = threadIdx.x;
    const int y0 = oy + 2*ty, x0 = ox + 2*tx;
    const int map[4] = {0, 1, 1, 2};
    float acc[4] = {0.f, 0.f, 0.f, 0.f};
    #pragma unroll 1
    for (int ic = 0; ic < 16; ic++) {
        float v[3][3];
        #pragma unroll
        for (int a = 0; a < 3; a++)
            #pragma unroll
            for (int c = 0; c < 3; c++)
                v[a][c] = s_g[(ic*18 + ty + a)*18 + tx + c];
        const float* w = &s_w[ic*9];
        #pragma unroll
        for (int t = 0; t < 9; t++) {
            int ky = t / 3, kx = t - ky*3;
            float wt = w[t];
            #pragma unroll
            for (int dy = 0; dy < 2; dy++)
                #pragma unroll
                for (int dx = 0; dx < 2; dx++)
                    acc[dy*2+dx] = fmaf(wt, v[map[dy+ky]][map[dx+kx]], acc[dy*2+dx]);
        }
    }
    float bb = s_bb[0];
    #pragma unroll
    for (int dy = 0; dy < 2; dy++)
        #pragma unroll
        for (int dx = 0; dx < 2; dx++) {
            float v = fminf(fmaxf(acc[dy*2+dx] + bb, -1.f), 1.f);
            out[(b*H0 + (y0+dy))*W0 + (x0+dx)] = v;
        }
}

// ---------------------------------------------------------------------------
__global__ void k_zero() { if (threadIdx.x == 0) g_loss = 0.0; }
__global__ void k_fin(float* __restrict__ out_loss) {
    if (threadIdx.x == 0)
        out_loss[0] = (float)(g_loss / (double)(BATCH * 1024 * DIM));
}

// ---------------------------------------------------------------------------
// Stream fork: k3 runs concurrently with k4+k5 (both depend only on k2's g_h2;
// disjoint writes). Fork/join via events — standard capture-legal pattern.
// kernel_launch is only invoked for correctness + capture (replays run the
// graph), so per-call stream/event creation is bounded and host-side only.
// ---------------------------------------------------------------------------
extern "C" void kernel_launch(void* const* d_in, const int* in_sizes, int n_in,
                              void* d_out, int out_size) {
    const float* x  = (const float*)d_in[0];
    const float* w1 = (const float*)d_in[1];
    const float* b1 = (const float*)d_in[2];
    const float* w2 = (const float*)d_in[3];
    const float* b2 = (const float*)d_in[4];
    const float* cb = (const float*)d_in[5];
    const float* w3 = (const float*)d_in[6];
    const float* b3 = (const float*)d_in[7];
    const float* w4 = (const float*)d_in[8];
    const float* b4 = (const float*)d_in[9];

    float* out      = (float*)d_out;
    float* out_idx  = out + BATCH*H0*W0;          // 2,097,152
    float* out_loss = out_idx + BATCH*H2*H2;      // +131,072

    cudaFuncSetAttribute(k2, cudaFuncAttributeMaxDynamicSharedMemorySize, K2_SMEM);
    cudaFuncSetAttribute(k3, cudaFuncAttributeMaxDynamicSharedMemorySize, K3_SMEM);
    cudaFuncSetAttribute(k4, cudaFuncAttributeMaxDynamicSharedMemorySize, K4_SMEM);

    cudaStream_t s2;
    cudaEvent_t evFork, evJoin;
    cudaStreamCreateWithFlags(&s2, cudaStreamNonBlocking);
    cudaEventCreateWithFlags(&evFork, cudaEventDisableTiming);
    cudaEventCreateWithFlags(&evJoin, cudaEventDisableTiming);

    // main chain
    k_zero<<<1, 32>>>();
    k1<<<dim3(8, BATCH), 256>>>(x, w1, b1);
    k2<<<dim3(4, BATCH), 256, K2_SMEM>>>(w2, b2);

    // fork: k3 on side stream
    cudaEventRecord(evFork, 0);
    cudaStreamWaitEvent(s2, evFork, 0);
    k3<<<1024, 256, K3_SMEM, s2>>>(cb, out_idx);
    cudaEventRecord(evJoin, s2);

    // decoder on main stream, concurrent with k3
    k4<<<dim3(4, BATCH), dim3(16,16), K4_SMEM>>>(w3, b3);
    k5<<<dim3(16, BATCH), dim3(16,16)>>>(w4, b4, out);

    // join and finalize (k_fin reads g_loss written by k3)
    cudaStreamWaitEvent(0, evJoin, 0);
    k_fin<<<1, 32>>>(out_loss);
}